// round 12
// baseline (speedup 1.0000x reference)
#include <cuda_runtime.h>
#include <cuda_bf16.h>
#include <cstdint>

#define D_MODEL 2048
#define B_SZ    64
#define KV_LEN  4096
#define N_HEAD  16
#define HDIM    128
#define QKV_N   2304
#define FF_DIM  8192
#define NITEM   32         // KV items per batch (128 rows each)
#define NPART   32         // one partial per item (rg merged in-CTA)

typedef unsigned long long ull;

// ---------------- scratch ----------------
__device__ float g_res1[B_SZ * D_MODEL];
__device__ float g_hs1 [B_SZ * D_MODEL];
__device__ float g_qkv [B_SZ * QKV_N];
__device__ float g_attn[B_SZ * D_MODEL];
__device__ float g_tmp [B_SZ * D_MODEL];
__device__ float g_hs2 [B_SZ * D_MODEL];
__device__ float g_mid [B_SZ * FF_DIM];
__device__ float g_part[6291456];                   // split-K partials (fits 32*64*2304)
__device__ float g_m  [B_SZ * N_HEAD * NPART];
__device__ float g_l  [B_SZ * N_HEAD * NPART];
__device__ float g_acc[B_SZ * N_HEAD * NPART * HDIM];   // 16.8 MB

// ---------------- helpers ----------------
__device__ __forceinline__ float warp_sum(float v) {
#pragma unroll
    for (int o = 16; o; o >>= 1) v += __shfl_xor_sync(0xffffffffu, v, o);
    return v;
}
__device__ __forceinline__ ull pk2(float x, float y) {
    ull r;
    asm("mov.b64 %0, {%1,%2};" : "=l"(r) : "f"(x), "f"(y));
    return r;
}
__device__ __forceinline__ void upk2(float& x, float& y, ull p) {
    asm("mov.b64 {%0,%1}, %2;" : "=f"(x), "=f"(y) : "l"(p));
}
__device__ __forceinline__ ull ffma2(ull a, ull b, ull c) {
    ull d;
    asm("fma.rn.f32x2 %0, %1, %2, %3;" : "=l"(d) : "l"(a), "l"(b), "l"(c));
    return d;
}
__device__ __forceinline__ ull mul2(ull a, ull b) {
    ull d;
    asm("mul.rn.f32x2 %0, %1, %2;" : "=l"(d) : "l"(a), "l"(b));
    return d;
}
__device__ __forceinline__ ull add2(ull a, ull b) {
    ull d;
    asm("add.rn.f32x2 %0, %1, %2;" : "=l"(d) : "l"(a), "l"(b));
    return d;
}
__device__ __forceinline__ uint32_t s2u(const void* p) {
    return (uint32_t)__cvta_generic_to_shared(p);
}

// bulk TMA 1D copies
__device__ __forceinline__ void bulk_load(uint32_t smem_dst, const void* gmem_src,
                                          uint32_t bytes, uint32_t mbar) {
    asm volatile(
        "cp.async.bulk.shared::cluster.global.mbarrier::complete_tx::bytes [%0], [%1], %2, [%3];"
        :: "r"(smem_dst), "l"(gmem_src), "r"(bytes), "r"(mbar) : "memory");
}
__device__ __forceinline__ void bulk_store(void* gmem_dst, uint32_t smem_src, uint32_t bytes) {
    asm volatile(
        "cp.async.bulk.global.shared::cta.bulk_group [%0], [%1], %2;"
        :: "l"(gmem_dst), "r"(smem_src), "r"(bytes) : "memory");
}
#define BULK_COMMIT()      asm volatile("cp.async.bulk.commit_group;" ::: "memory")
#define BULK_WAIT_READ0()  asm volatile("cp.async.bulk.wait_group.read 0;" ::: "memory")
#define MBAR_INIT(a, n)    asm volatile("mbarrier.init.shared.b64 [%0], %1;" :: "r"(a), "r"(n) : "memory")
#define MBAR_EXPECT(a, b)  asm volatile("mbarrier.arrive.expect_tx.shared.b64 _, [%0], %1;" :: "r"(a), "r"(b) : "memory")

__device__ __forceinline__ void mbar_wait(uint32_t mbar, uint32_t parity) {
    uint32_t done;
    asm volatile(
        "{\n\t.reg .pred p;\n\t"
        "mbarrier.try_wait.parity.acquire.cta.shared::cta.b64 p, [%1], %2;\n\t"
        "selp.b32 %0, 1, 0, p;\n\t}"
        : "=r"(done) : "r"(mbar), "r"(parity) : "memory");
    if (!done) {
        asm volatile(
            "{\n\t.reg .pred P1;\n\t"
            "WL_%=:\n\t"
            "mbarrier.try_wait.parity.acquire.cta.shared::cta.b64 P1, [%0], %1, 0x989680;\n\t"
            "@P1 bra.uni WD_%=;\n\t"
            "bra.uni WL_%=;\n\t"
            "WD_%=:\n\t}"
            :: "r"(mbar), "r"(parity) : "memory");
    }
}

// ---------------- fused residual-add + LayerNorm ----------------
__global__ void __launch_bounds__(256) add_ln_kernel(
    const float* __restrict__ a, const float* __restrict__ b,
    const float* __restrict__ w, const float* __restrict__ bias,
    float* __restrict__ res_out, float* __restrict__ ln_out)
{
    __shared__ float sh[33];
    const int row = blockIdx.x, tid = threadIdx.x;
    const int lane = tid & 31, wid = tid >> 5;

    const float4* a4 = (const float4*)(a + (size_t)row * D_MODEL);
    const float4* b4 = (const float4*)(b + (size_t)row * D_MODEL);
    float4 v0 = a4[tid], v1 = a4[tid + 256];
    float4 u0 = b4[tid], u1 = b4[tid + 256];
    v0.x += u0.x; v0.y += u0.y; v0.z += u0.z; v0.w += u0.w;
    v1.x += u1.x; v1.y += u1.y; v1.z += u1.z; v1.w += u1.w;

    float s = v0.x + v0.y + v0.z + v0.w + v1.x + v1.y + v1.z + v1.w;
    s = warp_sum(s);
    if (lane == 0) sh[wid] = s;
    __syncthreads();
    if (wid == 0) {
        float r = (lane < 8) ? sh[lane] : 0.f;
        r = warp_sum(r);
        if (lane == 0) sh[32] = r;
    }
    __syncthreads();
    const float mean = sh[32] * (1.0f / D_MODEL);

    float d0 = v0.x - mean, d1 = v0.y - mean, d2 = v0.z - mean, d3 = v0.w - mean;
    float d4 = v1.x - mean, d5 = v1.y - mean, d6 = v1.z - mean, d7 = v1.w - mean;
    float vs = d0*d0 + d1*d1 + d2*d2 + d3*d3 + d4*d4 + d5*d5 + d6*d6 + d7*d7;
    vs = warp_sum(vs);
    if (lane == 0) sh[wid] = vs;
    __syncthreads();
    if (wid == 0) {
        float r = (lane < 8) ? sh[lane] : 0.f;
        r = warp_sum(r);
        if (lane == 0) sh[32] = r;
    }
    __syncthreads();
    const float rstd = rsqrtf(sh[32] * (1.0f / D_MODEL) + 1e-5f);

    float4* ro = (float4*)(res_out + (size_t)row * D_MODEL);
    ro[tid] = v0; ro[tid + 256] = v1;

    const float4* w4 = (const float4*)w;
    const float4* c4 = (const float4*)bias;
    float4 W0 = w4[tid], W1 = w4[tid + 256], B0 = c4[tid], B1 = c4[tid + 256];
    float4 o0, o1;
    o0.x = d0 * rstd * W0.x + B0.x;  o0.y = d1 * rstd * W0.y + B0.y;
    o0.z = d2 * rstd * W0.z + B0.z;  o0.w = d3 * rstd * W0.w + B0.w;
    o1.x = d4 * rstd * W1.x + B1.x;  o1.y = d5 * rstd * W1.y + B1.y;
    o1.z = d6 * rstd * W1.z + B1.z;  o1.w = d7 * rstd * W1.w + B1.w;
    float4* lo = (float4*)(ln_out + (size_t)row * D_MODEL);
    lo[tid] = o0; lo[tid + 256] = o1;
}

// ---------------- split-K GEMM: BM=64, BN=256, BK=16, 2-stage smem, 1 sync/tile ----------------
__global__ void __launch_bounds__(256, 2) gemm_splitk_kernel(
    const float* __restrict__ A, const float* __restrict__ W,
    float* __restrict__ P, int K, int N, int klen)
{
    __shared__ ull   As2[2][16][66];
    __shared__ float Bs [2][16][256];
    const int n0 = blockIdx.x * 256;
    const int k0 = blockIdx.y * klen;
    const int tid = threadIdx.x;
    const int w = tid >> 5, lane = tid & 31;
    const int wm = w >> 2, wn = w & 3;
    const int lm = lane >> 3, ln = lane & 7;
    const int mbase = wm * 32 + lm * 8;
    const int nbase = wn * 64 + ln * 8;

    int am[4], ak[4], brow[4], bcol[4];
#pragma unroll
    for (int l = 0; l < 4; l++) {
        int ia = tid + l * 256;
        am[l] = ia >> 4; ak[l] = ia & 15;
        brow[l] = ia >> 6; bcol[l] = (ia & 63) * 4;
    }

    ull acc[8][4];
#pragma unroll
    for (int i = 0; i < 8; i++)
#pragma unroll
        for (int j = 0; j < 4; j++) acc[i][j] = 0ULL;

    float  a_r[4];
    float4 b_r[4];
#pragma unroll
    for (int l = 0; l < 4; l++) a_r[l] = A[(size_t)am[l] * K + k0 + ak[l]];
#pragma unroll
    for (int l = 0; l < 4; l++)
        b_r[l] = *(const float4*)&W[(size_t)(k0 + brow[l]) * N + n0 + bcol[l]];
#pragma unroll
    for (int l = 0; l < 4; l++) As2[0][ak[l]][am[l]] = pk2(a_r[l], a_r[l]);
#pragma unroll
    for (int l = 0; l < 4; l++) *(float4*)&Bs[0][brow[l]][bcol[l]] = b_r[l];

    const int nt = klen >> 4;
    for (int t = 0; t < nt; t++) {
        const int cur = t & 1;
        if (t + 1 < nt) {
            const int kb = k0 + (t + 1) * 16;
#pragma unroll
            for (int l = 0; l < 4; l++) a_r[l] = A[(size_t)am[l] * K + kb + ak[l]];
#pragma unroll
            for (int l = 0; l < 4; l++)
                b_r[l] = *(const float4*)&W[(size_t)(kb + brow[l]) * N + n0 + bcol[l]];
        }
        __syncthreads();

#pragma unroll
        for (int kk = 0; kk < 16; kk++) {
            float4 bf0 = *(const float4*)&Bs[cur][kk][nbase];
            float4 bf1 = *(const float4*)&Bs[cur][kk][nbase + 4];
            ull bb0 = pk2(bf0.x, bf0.y), bb1 = pk2(bf0.z, bf0.w);
            ull bb2 = pk2(bf1.x, bf1.y), bb3 = pk2(bf1.z, bf1.w);
#pragma unroll
            for (int q = 0; q < 4; q++) {
                ulonglong2 aa = *(const ulonglong2*)&As2[cur][kk][mbase + 2 * q];
                acc[2*q][0]   = ffma2(aa.x, bb0, acc[2*q][0]);
                acc[2*q][1]   = ffma2(aa.x, bb1, acc[2*q][1]);
                acc[2*q][2]   = ffma2(aa.x, bb2, acc[2*q][2]);
                acc[2*q][3]   = ffma2(aa.x, bb3, acc[2*q][3]);
                acc[2*q+1][0] = ffma2(aa.y, bb0, acc[2*q+1][0]);
                acc[2*q+1][1] = ffma2(aa.y, bb1, acc[2*q+1][1]);
                acc[2*q+1][2] = ffma2(aa.y, bb2, acc[2*q+1][2]);
                acc[2*q+1][3] = ffma2(aa.y, bb3, acc[2*q+1][3]);
            }
        }

        if (t + 1 < nt) {
            const int nxt = cur ^ 1;
#pragma unroll
            for (int l = 0; l < 4; l++) As2[nxt][ak[l]][am[l]] = pk2(a_r[l], a_r[l]);
#pragma unroll
            for (int l = 0; l < 4; l++) *(float4*)&Bs[nxt][brow[l]][bcol[l]] = b_r[l];
        }
    }
    float* Pp = P + (size_t)blockIdx.y * 64 * (size_t)N;
#pragma unroll
    for (int i = 0; i < 8; i++) {
        size_t base = (size_t)(mbase + i) * N + n0 + nbase;
        *(ull*)&Pp[base]     = acc[i][0];
        *(ull*)&Pp[base + 2] = acc[i][1];
        *(ull*)&Pp[base + 4] = acc[i][2];
        *(ull*)&Pp[base + 6] = acc[i][3];
    }
}

// ---------------- split-K reduce + bias (+ optional tanh-gelu) ----------------
__global__ void __launch_bounds__(256) reduce_kernel(
    const float* __restrict__ P, int S, int total, int N,
    const float* __restrict__ bias, float* __restrict__ dst, int act)
{
    int idx = blockIdx.x * 256 + threadIdx.x;
    if (idx >= total) return;
    float v = 0.f;
    for (int s = 0; s < S; s++) v += P[(size_t)s * total + idx];
    v += bias[idx % N];
    if (act == 1) {
        float x3 = v * v * v;
        v = 0.5f * v * (1.0f + tanhf(0.7978845608028654f * (v + 0.044715f * x3)));
    }
    dst[idx] = v;
}

// ---------------- attention: bulk-TMA, 2 linear stages + chunk-major K buffer ----------------
// Item w in [0,2048): b=w>>5, sp=w&31 -> 128 contiguous KV rows = 4 tiles of 32 rows (32KB).
// Stage is linear (TMA layout). V is read DIRECTLY from the stage (conflict-free).
// K alone is repacked chunk-major into kbuf with a quad-xor. At item end, the two
// row-group warps (rg=0/1) merge their partials in-CTA via kbuf -> NPART=32.
#define TILE_R 32
#define TILE_F (TILE_R * 256)      // 8192 floats = 32KB
#define ATTN_T 256

__global__ void __launch_bounds__(ATTN_T, 2) attn_kernel(
    const float* __restrict__ past, const float* __restrict__ qkv,
    const int* __restrict__ key_length,
    float* __restrict__ out_kv,
    float* __restrict__ m_part, float* __restrict__ l_part, float* __restrict__ acc_part)
{
    extern __shared__ float sm[];
    float* q_s  = sm;                         // 2048 floats
    float* kbuf = sm + 2048 + 16;             // 4096 floats (16KB), chunk-major K / merge buf
    float* stg0 = kbuf + 32 * 32 * 4;         // linear stage 0 (8192 floats)
    float* stg1 = stg0 + TILE_F;              // linear stage 1
    const uint32_t mb0 = s2u(sm + 2048);
    const uint32_t mb1 = mb0 + 8;

    const int tid = threadIdx.x, lane = tid & 31, warp = tid >> 5;
    const int hg = warp >> 1, rg = warp & 1, h0 = hg * 4;
    const int r16 = lane & 15, hs = lane >> 4;
    const int myrow = rg * 16 + r16;
    const int upd = key_length[0] - 1;

    if (tid == 0) { MBAR_INIT(mb0, 1); MBAR_INIT(mb1, 1); }
    __syncthreads();
    int ph0 = 0, ph1 = 0;

    for (int w = blockIdx.x; w < B_SZ * NITEM; w += 296) {
        const int b = w >> 5, sp = w & 31;
        const float* qb = qkv + (size_t)b * QKV_N;
        const float4* qnew = (const float4*)(qb + D_MODEL);
        const char* src_b = (const char*)past   + ((size_t)b * KV_LEN) * 1024;
        char*       dst_b = (char*)      out_kv + ((size_t)b * KV_LEN) * 1024;
        const int kvbase = sp * 128;

        __syncthreads();   // all threads done with q_s / kbuf from previous item

        for (int i = tid; i < 2048; i += ATTN_T)
            q_s[i] = qb[i] * 0.08838834764831845f;

        if (tid == 0) {
            BULK_WAIT_READ0();   // prior item's bulk stores have read the stages
            MBAR_EXPECT(mb0, TILE_F * 4);
            bulk_load(s2u(stg0), src_b + (size_t)kvbase * 1024, TILE_F * 4, mb0);
            MBAR_EXPECT(mb1, TILE_F * 4);
            bulk_load(s2u(stg1), src_b + (size_t)(kvbase + 32) * 1024, TILE_F * 4, mb1);
        }

        float m0 = -3.4e38f, m1 = -3.4e38f, l0 = 0.f, l1 = 0.f;
        ull acc0[4], acc1[4];
#pragma unroll
        for (int i = 0; i < 4; i++) { acc0[i] = 0ULL; acc1[i] = 0ULL; }

#pragma unroll 1
        for (int t = 0; t < 4; t++) {
            const int st = t & 1;
            float* s = st ? stg1 : stg0;
            if (st) { mbar_wait(mb1, ph1); ph1 ^= 1; }
            else    { mbar_wait(mb0, ph0); ph0 ^= 1; }
            const int kv0 = kvbase + t * 32;
            const bool hasupd = (upd >= kv0 && upd < kv0 + TILE_R);

            // rare: patch the updated KV row into the linear stage
            if (hasupd && tid < 64) {
                float4 val = qnew[tid];
                *(float4*)(s + (upd - kv0) * 256 + tid * 4) = val;
            }
            __syncthreads();   // patch visible; kbuf free (prev compute done)

            if (tid == 0) {
                if (hasupd) asm volatile("fence.proxy.async.shared::cta;" ::: "memory");
                bulk_store(dst_b + (size_t)kv0 * 1024, s2u(s), TILE_F * 4);
                BULK_COMMIT();
            }

            // repack K only: linear stage -> chunk-major kbuf (quad-xor)
#pragma unroll
            for (int li = 0; li < 4; li++) {
                int r = warp + li * 8;        // row 0..31
                float4 val = *(const float4*)(s + r * 256 + lane * 4);
                *(float4*)(kbuf + ((lane * 32 + (r ^ (lane & 7))) << 2)) = val;
            }
            __syncthreads();   // kbuf ready

            // ---- scores from kbuf (chunk-major): q broadcast, k 2-wf floor ----
            const float* qA = q_s + (h0 + 2 * hs) * HDIM;
            const float* qB = qA + HDIM;
            ull xa0 = 0ULL, xa1 = 0ULL, xb0 = 0ULL, xb1 = 0ULL;
#pragma unroll 8
            for (int d4 = 0; d4 < 32; d4++) {
                ulonglong2 k2 = *(const ulonglong2*)(kbuf + ((d4 * 32 + (myrow ^ (d4 & 7))) << 2));
                ulonglong2 qa2 = *(const ulonglong2*)(qA + d4 * 4);
                ulonglong2 qb2 = *(const ulonglong2*)(qB + d4 * 4);
                xa0 = ffma2(k2.x, qa2.x, xa0);
                xa1 = ffma2(k2.y, qa2.y, xa1);
                xb0 = ffma2(k2.x, qb2.x, xb0);
                xb1 = ffma2(k2.y, qb2.y, xb1);
            }
            ull xap = add2(xa0, xa1), xbp = add2(xb0, xb1);
            float xal, xah, xbl, xbh;
            upk2(xal, xah, xap);
            upk2(xbl, xbh, xbp);
            float xa = xal + xah, xb = xbl + xbh;

            float ta = xa, tb = xb;
#pragma unroll
            for (int o = 8; o; o >>= 1) {
                ta = fmaxf(ta, __shfl_xor_sync(0xffffffffu, ta, o));
                tb = fmaxf(tb, __shfl_xor_sync(0xffffffffu, tb, o));
            }
            float mna = fmaxf(m0, ta), mnb = fmaxf(m1, tb);
            float ca = __expf(m0 - mna), cb = __expf(m1 - mnb);
            float pa = __expf(xa - mna), pb = __expf(xb - mnb);
            float sa = pa, sb = pb;
#pragma unroll
            for (int o = 8; o; o >>= 1) {
                sa += __shfl_xor_sync(0xffffffffu, sa, o);
                sb += __shfl_xor_sync(0xffffffffu, sb, o);
            }
            l0 = l0 * ca + sa;  l1 = l1 * cb + sb;
            m0 = mna;           m1 = mnb;
            ull ca2 = pk2(ca, ca), cb2 = pk2(cb, cb);
#pragma unroll
            for (int i = 0; i < 4; i++) { acc0[i] = mul2(acc0[i], ca2); acc1[i] = mul2(acc1[i], cb2); }

            // ---- P @ V directly from the linear stage (conflict-free) ----
            const int rowbase = rg * 16;
#pragma unroll
            for (int r = 0; r < 16; r++) {
                int src = (lane & 16) | r;
                float p0 = __shfl_sync(0xffffffffu, pa, src);
                float p1 = __shfl_sync(0xffffffffu, pb, src);
                ull p02 = pk2(p0, p0), p12 = pk2(p1, p1);
                const float* vr = s + (rowbase + r) * 256 + 128;
                ulonglong2 v01 = *(const ulonglong2*)(vr + r16 * 4);
                ulonglong2 v23 = *(const ulonglong2*)(vr + 64 + r16 * 4);
                acc0[0] = ffma2(p02, v01.x, acc0[0]);
                acc0[1] = ffma2(p02, v01.y, acc0[1]);
                acc0[2] = ffma2(p02, v23.x, acc0[2]);
                acc0[3] = ffma2(p02, v23.y, acc0[3]);
                acc1[0] = ffma2(p12, v01.x, acc1[0]);
                acc1[1] = ffma2(p12, v01.y, acc1[1]);
                acc1[2] = ffma2(p12, v23.x, acc1[2]);
                acc1[3] = ffma2(p12, v23.y, acc1[3]);
            }
            __syncthreads();   // stage fully consumed (V reads + repack done)

            if (tid == 0 && t + 2 < 4) {
                BULK_WAIT_READ0();      // bulk store of this stage has read its data
                uint32_t mb = st ? mb1 : mb0;
                MBAR_EXPECT(mb, TILE_F * 4);
                bulk_load(s2u(s), src_b + (size_t)(kvbase + (t + 2) * 32) * 1024, TILE_F * 4, mb);
            }
        }

        // ---- in-CTA merge of rg=1 into rg=0 (same head/dim layout), then flush ----
        ull*   xbuf  = (ull*)kbuf;             // 1024 ull (8 KB) acc exchange
        float* mlbuf = kbuf + 2048;            // 512 floats m/l exchange
        if (rg == 1) {
            ull* dst = xbuf + ((size_t)hg * 32 + lane) * 8;
#pragma unroll
            for (int i = 0; i < 4; i++) { dst[i] = acc0[i]; dst[4 + i] = acc1[i]; }
            float* ml = mlbuf + (hg * 32 + lane) * 4;
            ml[0] = m0; ml[1] = l0; ml[2] = m1; ml[3] = l1;
        }
        __syncthreads();
        if (rg == 0) {
            const ull* srcp = xbuf + ((size_t)hg * 32 + lane) * 8;
            const float* ml = mlbuf + (hg * 32 + lane) * 4;
            float m0b = ml[0], l0b = ml[1], m1b = ml[2], l1b = ml[3];
            float mA = fmaxf(m0, m0b), mB = fmaxf(m1, m1b);
            float c0a = __expf(m0 - mA),  c0b = __expf(m0b - mA);
            float c1a = __expf(m1 - mB),  c1b = __expf(m1b - mB);
            l0 = l0 * c0a + l0b * c0b;
            l1 = l1 * c1a + l1b * c1b;
            ull c0a2 = pk2(c0a, c0a), c0b2 = pk2(c0b, c0b);
            ull c1a2 = pk2(c1a, c1a), c1b2 = pk2(c1b, c1b);
#pragma unroll
            for (int i = 0; i < 4; i++) {
                acc0[i] = add2(mul2(acc0[i], c0a2), mul2(srcp[i],     c0b2));
                acc1[i] = add2(mul2(acc1[i], c1a2), mul2(srcp[4 + i], c1b2));
            }
            const int ghA = h0 + 2 * hs, ghB = ghA + 1;
            const int phA = (b * N_HEAD + ghA) * NITEM + sp;
            const int phB = (b * N_HEAD + ghB) * NITEM + sp;
            if (r16 == 0) {
                m_part[phA] = mA; l_part[phA] = l0;
                m_part[phB] = mB; l_part[phB] = l1;
            }
            ull* dA = (ull*)(acc_part + (size_t)phA * HDIM);
            ull* dB = (ull*)(acc_part + (size_t)phB * HDIM);
            dA[r16 * 2]          = acc0[0];
            dA[r16 * 2 + 1]      = acc0[1];
            dA[32 + r16 * 2]     = acc0[2];
            dA[32 + r16 * 2 + 1] = acc0[3];
            dB[r16 * 2]          = acc1[0];
            dB[r16 * 2 + 1]      = acc1[1];
            dB[32 + r16 * 2]     = acc1[2];
            dB[32 + r16 * 2 + 1] = acc1[3];
        }
    }
}

// ---------------- combine split partial softmax results ----------------
__global__ void __launch_bounds__(128) attn_combine_kernel(
    const float* __restrict__ m_part, const float* __restrict__ l_part,
    const float* __restrict__ acc_part, float* __restrict__ attn_out)
{
    const int bh = blockIdx.x;
    const int d = threadIdx.x;
    float mm = -3.4e38f;
#pragma unroll 8
    for (int s = 0; s < NPART; s++) mm = fmaxf(mm, m_part[bh * NPART + s]);
    float L = 0.f, o = 0.f;
#pragma unroll 8
    for (int s = 0; s < NPART; s++) {
        float w = __expf(m_part[bh * NPART + s] - mm);
        L += l_part[bh * NPART + s] * w;
        o += acc_part[(size_t)(bh * NPART + s) * HDIM + d] * w;
    }
    int b = bh >> 4, h = bh & 15;
    attn_out[(size_t)b * D_MODEL + h * HDIM + d] = o / L;
}

// ---------------- launch ----------------
extern "C" void kernel_launch(void* const* d_in, const int* in_sizes, int n_in,
                              void* d_out, int out_size)
{
    const float* hidden = (const float*)d_in[0];
    const float* resid  = (const float*)d_in[1];
    const float* past   = (const float*)d_in[2];
    // d_in[3] = attention_mask (all-true; no-op)
    const int*   keylen = (const int*)d_in[4];
    const float* aaw = (const float*)d_in[5];
    const float* aab = (const float*)d_in[6];
    const float* apw = (const float*)d_in[7];
    const float* apb = (const float*)d_in[8];
    const float* l1w = (const float*)d_in[9];
    const float* l1b = (const float*)d_in[10];
    const float* l2w = (const float*)d_in[11];
    const float* l2b = (const float*)d_in[12];
    const float* mfw = (const float*)d_in[13];
    const float* mfb = (const float*)d_in[14];
    const float* mpw = (const float*)d_in[15];
    const float* mpb = (const float*)d_in[16];

    float* out     = (float*)d_out;
    float* out_hs  = out;
    float* out_res = out + B_SZ * D_MODEL;
    float* out_kv  = out + 2 * B_SZ * D_MODEL;

    float *res1, *hs1, *qkv, *attn, *tmp, *hs2, *mid, *part, *pm, *pl, *pacc;
    cudaGetSymbolAddress((void**)&res1, g_res1);
    cudaGetSymbolAddress((void**)&hs1,  g_hs1);
    cudaGetSymbolAddress((void**)&qkv,  g_qkv);
    cudaGetSymbolAddress((void**)&attn, g_attn);
    cudaGetSymbolAddress((void**)&tmp,  g_tmp);
    cudaGetSymbolAddress((void**)&hs2,  g_hs2);
    cudaGetSymbolAddress((void**)&mid,  g_mid);
    cudaGetSymbolAddress((void**)&part, g_part);
    cudaGetSymbolAddress((void**)&pm,   g_m);
    cudaGetSymbolAddress((void**)&pl,   g_l);
    cudaGetSymbolAddress((void**)&pacc, g_acc);

    const int attn_smem = (2048 + 16 + 32 * 32 * 4 + 2 * TILE_F) * sizeof(float);   // ~90 KB/CTA
    cudaFuncSetAttribute(attn_kernel, cudaFuncAttributeMaxDynamicSharedMemorySize, attn_smem);

    // 1) residual = hidden + residual ; hs1 = LN1(residual)
    add_ln_kernel<<<64, 256>>>(hidden, resid, l1w, l1b, res1, hs1);

    // 2) qkv = hs1 @ aaw + aab   (N=2304: 9 nb x 32 splits = 288 CTAs, klen 64)
    gemm_splitk_kernel<<<dim3(9, 32), 256>>>(hs1, aaw, part, 2048, 2304, 64);
    reduce_kernel<<<(B_SZ * QKV_N + 255) / 256, 256>>>(part, 32, B_SZ * QKV_N, QKV_N, aab, qkv, 0);

    // 3) attention + KV-cache update + fused layer_past copy-out
    attn_kernel<<<296, ATTN_T, attn_smem>>>(past, qkv, keylen, out_kv, pm, pl, pacc);
    attn_combine_kernel<<<B_SZ * N_HEAD, 128>>>(pm, pl, pacc, attn);

    // 4) proj = attn @ apw + apb  (N=2048: 8 nb x 32 splits = 256 CTAs, klen 64)
    gemm_splitk_kernel<<<dim3(8, 32), 256>>>(attn, apw, part, 2048, 2048, 64);
    reduce_kernel<<<(B_SZ * D_MODEL + 255) / 256, 256>>>(part, 32, B_SZ * D_MODEL, D_MODEL, apb, tmp, 0);

    // 5) residual2 = proj + residual1 (-> d_out) ; hs2 = LN2(residual2)
    add_ln_kernel<<<64, 256>>>(tmp, res1, l2w, l2b, out_res, hs2);

    // 6) mid = gelu(hs2 @ mfw + mfb)  (N=8192: 32 nb x 8 splits = 256 CTAs, klen 256)
    gemm_splitk_kernel<<<dim3(32, 8), 256>>>(hs2, mfw, part, 2048, 8192, 256);
    reduce_kernel<<<(B_SZ * FF_DIM + 255) / 256, 256>>>(part, 8, B_SZ * FF_DIM, FF_DIM, mfb, mid, 1);

    // 7) out_hs = mid @ mpw + mpb   (N=2048: 8 nb x 32 splits = 256 CTAs, klen 256)
    gemm_splitk_kernel<<<dim3(8, 32), 256>>>(mid, mpw, part, 8192, 2048, 256);
    reduce_kernel<<<(B_SZ * D_MODEL + 255) / 256, 256>>>(part, 32, B_SZ * D_MODEL, D_MODEL, mpb, out_hs, 0);
}

// round 13
// speedup vs baseline: 1.5926x; 1.5926x over previous
#include <cuda_runtime.h>
#include <cuda_bf16.h>
#include <cstdint>

#define D_MODEL 2048
#define B_SZ    64
#define KV_LEN  4096
#define N_HEAD  16
#define HDIM    128
#define QKV_N   2304
#define FF_DIM  8192
#define NITEM   32         // KV items per batch (128 rows each)
#define NPART   32         // one partial per item (rg merged in-CTA)

typedef unsigned long long ull;

// ---------------- scratch ----------------
__device__ float g_res1[B_SZ * D_MODEL];
__device__ float g_hs1 [B_SZ * D_MODEL];
__device__ float g_qkv [B_SZ * QKV_N];
__device__ float g_attn[B_SZ * D_MODEL];
__device__ float g_tmp [B_SZ * D_MODEL];
__device__ float g_hs2 [B_SZ * D_MODEL];
__device__ float g_mid [B_SZ * FF_DIM];
__device__ float g_part[6291456];                   // split-K partials (fits 32*64*2304)
__device__ float g_m  [B_SZ * N_HEAD * NPART];
__device__ float g_l  [B_SZ * N_HEAD * NPART];
__device__ float g_acc[B_SZ * N_HEAD * NPART * HDIM];   // 16.8 MB

// ---------------- helpers ----------------
__device__ __forceinline__ float warp_sum(float v) {
#pragma unroll
    for (int o = 16; o; o >>= 1) v += __shfl_xor_sync(0xffffffffu, v, o);
    return v;
}
__device__ __forceinline__ ull pk2(float x, float y) {
    ull r;
    asm("mov.b64 %0, {%1,%2};" : "=l"(r) : "f"(x), "f"(y));
    return r;
}
__device__ __forceinline__ void upk2(float& x, float& y, ull p) {
    asm("mov.b64 {%0,%1}, %2;" : "=f"(x), "=f"(y) : "l"(p));
}
__device__ __forceinline__ ull ffma2(ull a, ull b, ull c) {
    ull d;
    asm("fma.rn.f32x2 %0, %1, %2, %3;" : "=l"(d) : "l"(a), "l"(b), "l"(c));
    return d;
}
__device__ __forceinline__ ull mul2(ull a, ull b) {
    ull d;
    asm("mul.rn.f32x2 %0, %1, %2;" : "=l"(d) : "l"(a), "l"(b));
    return d;
}
__device__ __forceinline__ ull add2(ull a, ull b) {
    ull d;
    asm("add.rn.f32x2 %0, %1, %2;" : "=l"(d) : "l"(a), "l"(b));
    return d;
}
__device__ __forceinline__ uint32_t s2u(const void* p) {
    return (uint32_t)__cvta_generic_to_shared(p);
}

// bulk TMA 1D copies
__device__ __forceinline__ void bulk_load(uint32_t smem_dst, const void* gmem_src,
                                          uint32_t bytes, uint32_t mbar) {
    asm volatile(
        "cp.async.bulk.shared::cluster.global.mbarrier::complete_tx::bytes [%0], [%1], %2, [%3];"
        :: "r"(smem_dst), "l"(gmem_src), "r"(bytes), "r"(mbar) : "memory");
}
__device__ __forceinline__ void bulk_store(void* gmem_dst, uint32_t smem_src, uint32_t bytes) {
    asm volatile(
        "cp.async.bulk.global.shared::cta.bulk_group [%0], [%1], %2;"
        :: "l"(gmem_dst), "r"(smem_src), "r"(bytes) : "memory");
}
#define BULK_COMMIT()      asm volatile("cp.async.bulk.commit_group;" ::: "memory")
#define BULK_WAIT_READ0()  asm volatile("cp.async.bulk.wait_group.read 0;" ::: "memory")
#define MBAR_INIT(a, n)    asm volatile("mbarrier.init.shared.b64 [%0], %1;" :: "r"(a), "r"(n) : "memory")
#define MBAR_EXPECT(a, b)  asm volatile("mbarrier.arrive.expect_tx.shared.b64 _, [%0], %1;" :: "r"(a), "r"(b) : "memory")

__device__ __forceinline__ void mbar_wait(uint32_t mbar, uint32_t parity) {
    uint32_t done;
    asm volatile(
        "{\n\t.reg .pred p;\n\t"
        "mbarrier.try_wait.parity.acquire.cta.shared::cta.b64 p, [%1], %2;\n\t"
        "selp.b32 %0, 1, 0, p;\n\t}"
        : "=r"(done) : "r"(mbar), "r"(parity) : "memory");
    if (!done) {
        asm volatile(
            "{\n\t.reg .pred P1;\n\t"
            "WL_%=:\n\t"
            "mbarrier.try_wait.parity.acquire.cta.shared::cta.b64 P1, [%0], %1, 0x989680;\n\t"
            "@P1 bra.uni WD_%=;\n\t"
            "bra.uni WL_%=;\n\t"
            "WD_%=:\n\t}"
            :: "r"(mbar), "r"(parity) : "memory");
    }
}

// ---------------- fused residual-add + LayerNorm ----------------
__global__ void __launch_bounds__(256) add_ln_kernel(
    const float* __restrict__ a, const float* __restrict__ b,
    const float* __restrict__ w, const float* __restrict__ bias,
    float* __restrict__ res_out, float* __restrict__ ln_out)
{
    __shared__ float sh[33];
    const int row = blockIdx.x, tid = threadIdx.x;
    const int lane = tid & 31, wid = tid >> 5;

    const float4* a4 = (const float4*)(a + (size_t)row * D_MODEL);
    const float4* b4 = (const float4*)(b + (size_t)row * D_MODEL);
    float4 v0 = a4[tid], v1 = a4[tid + 256];
    float4 u0 = b4[tid], u1 = b4[tid + 256];
    v0.x += u0.x; v0.y += u0.y; v0.z += u0.z; v0.w += u0.w;
    v1.x += u1.x; v1.y += u1.y; v1.z += u1.z; v1.w += u1.w;

    float s = v0.x + v0.y + v0.z + v0.w + v1.x + v1.y + v1.z + v1.w;
    s = warp_sum(s);
    if (lane == 0) sh[wid] = s;
    __syncthreads();
    if (wid == 0) {
        float r = (lane < 8) ? sh[lane] : 0.f;
        r = warp_sum(r);
        if (lane == 0) sh[32] = r;
    }
    __syncthreads();
    const float mean = sh[32] * (1.0f / D_MODEL);

    float d0 = v0.x - mean, d1 = v0.y - mean, d2 = v0.z - mean, d3 = v0.w - mean;
    float d4 = v1.x - mean, d5 = v1.y - mean, d6 = v1.z - mean, d7 = v1.w - mean;
    float vs = d0*d0 + d1*d1 + d2*d2 + d3*d3 + d4*d4 + d5*d5 + d6*d6 + d7*d7;
    vs = warp_sum(vs);
    if (lane == 0) sh[wid] = vs;
    __syncthreads();
    if (wid == 0) {
        float r = (lane < 8) ? sh[lane] : 0.f;
        r = warp_sum(r);
        if (lane == 0) sh[32] = r;
    }
    __syncthreads();
    const float rstd = rsqrtf(sh[32] * (1.0f / D_MODEL) + 1e-5f);

    float4* ro = (float4*)(res_out + (size_t)row * D_MODEL);
    ro[tid] = v0; ro[tid + 256] = v1;

    const float4* w4 = (const float4*)w;
    const float4* c4 = (const float4*)bias;
    float4 W0 = w4[tid], W1 = w4[tid + 256], B0 = c4[tid], B1 = c4[tid + 256];
    float4 o0, o1;
    o0.x = d0 * rstd * W0.x + B0.x;  o0.y = d1 * rstd * W0.y + B0.y;
    o0.z = d2 * rstd * W0.z + B0.z;  o0.w = d3 * rstd * W0.w + B0.w;
    o1.x = d4 * rstd * W1.x + B1.x;  o1.y = d5 * rstd * W1.y + B1.y;
    o1.z = d6 * rstd * W1.z + B1.z;  o1.w = d7 * rstd * W1.w + B1.w;
    float4* lo = (float4*)(ln_out + (size_t)row * D_MODEL);
    lo[tid] = o0; lo[tid + 256] = o1;
}

// ---------------- split-K GEMM: BM=64, BN=256, BK=16, 2-stage smem, 1 sync/tile ----------------
__global__ void __launch_bounds__(256, 2) gemm_splitk_kernel(
    const float* __restrict__ A, const float* __restrict__ W,
    float* __restrict__ P, int K, int N, int klen)
{
    __shared__ ull   As2[2][16][66];
    __shared__ float Bs [2][16][256];
    const int n0 = blockIdx.x * 256;
    const int k0 = blockIdx.y * klen;
    const int tid = threadIdx.x;
    const int w = tid >> 5, lane = tid & 31;
    const int wm = w >> 2, wn = w & 3;
    const int lm = lane >> 3, ln = lane & 7;
    const int mbase = wm * 32 + lm * 8;
    const int nbase = wn * 64 + ln * 8;

    int am[4], ak[4], brow[4], bcol[4];
#pragma unroll
    for (int l = 0; l < 4; l++) {
        int ia = tid + l * 256;
        am[l] = ia >> 4; ak[l] = ia & 15;
        brow[l] = ia >> 6; bcol[l] = (ia & 63) * 4;
    }

    ull acc[8][4];
#pragma unroll
    for (int i = 0; i < 8; i++)
#pragma unroll
        for (int j = 0; j < 4; j++) acc[i][j] = 0ULL;

    float  a_r[4];
    float4 b_r[4];
#pragma unroll
    for (int l = 0; l < 4; l++) a_r[l] = A[(size_t)am[l] * K + k0 + ak[l]];
#pragma unroll
    for (int l = 0; l < 4; l++)
        b_r[l] = *(const float4*)&W[(size_t)(k0 + brow[l]) * N + n0 + bcol[l]];
#pragma unroll
    for (int l = 0; l < 4; l++) As2[0][ak[l]][am[l]] = pk2(a_r[l], a_r[l]);
#pragma unroll
    for (int l = 0; l < 4; l++) *(float4*)&Bs[0][brow[l]][bcol[l]] = b_r[l];

    const int nt = klen >> 4;
    for (int t = 0; t < nt; t++) {
        const int cur = t & 1;
        if (t + 1 < nt) {
            const int kb = k0 + (t + 1) * 16;
#pragma unroll
            for (int l = 0; l < 4; l++) a_r[l] = A[(size_t)am[l] * K + kb + ak[l]];
#pragma unroll
            for (int l = 0; l < 4; l++)
                b_r[l] = *(const float4*)&W[(size_t)(kb + brow[l]) * N + n0 + bcol[l]];
        }
        __syncthreads();

#pragma unroll
        for (int kk = 0; kk < 16; kk++) {
            float4 bf0 = *(const float4*)&Bs[cur][kk][nbase];
            float4 bf1 = *(const float4*)&Bs[cur][kk][nbase + 4];
            ull bb0 = pk2(bf0.x, bf0.y), bb1 = pk2(bf0.z, bf0.w);
            ull bb2 = pk2(bf1.x, bf1.y), bb3 = pk2(bf1.z, bf1.w);
#pragma unroll
            for (int q = 0; q < 4; q++) {
                ulonglong2 aa = *(const ulonglong2*)&As2[cur][kk][mbase + 2 * q];
                acc[2*q][0]   = ffma2(aa.x, bb0, acc[2*q][0]);
                acc[2*q][1]   = ffma2(aa.x, bb1, acc[2*q][1]);
                acc[2*q][2]   = ffma2(aa.x, bb2, acc[2*q][2]);
                acc[2*q][3]   = ffma2(aa.x, bb3, acc[2*q][3]);
                acc[2*q+1][0] = ffma2(aa.y, bb0, acc[2*q+1][0]);
                acc[2*q+1][1] = ffma2(aa.y, bb1, acc[2*q+1][1]);
                acc[2*q+1][2] = ffma2(aa.y, bb2, acc[2*q+1][2]);
                acc[2*q+1][3] = ffma2(aa.y, bb3, acc[2*q+1][3]);
            }
        }

        if (t + 1 < nt) {
            const int nxt = cur ^ 1;
#pragma unroll
            for (int l = 0; l < 4; l++) As2[nxt][ak[l]][am[l]] = pk2(a_r[l], a_r[l]);
#pragma unroll
            for (int l = 0; l < 4; l++) *(float4*)&Bs[nxt][brow[l]][bcol[l]] = b_r[l];
        }
    }
    float* Pp = P + (size_t)blockIdx.y * 64 * (size_t)N;
#pragma unroll
    for (int i = 0; i < 8; i++) {
        size_t base = (size_t)(mbase + i) * N + n0 + nbase;
        *(ull*)&Pp[base]     = acc[i][0];
        *(ull*)&Pp[base + 2] = acc[i][1];
        *(ull*)&Pp[base + 4] = acc[i][2];
        *(ull*)&Pp[base + 6] = acc[i][3];
    }
}

// ---------------- split-K reduce + bias (+ optional tanh-gelu) ----------------
__global__ void __launch_bounds__(256) reduce_kernel(
    const float* __restrict__ P, int S, int total, int N,
    const float* __restrict__ bias, float* __restrict__ dst, int act)
{
    int idx = blockIdx.x * 256 + threadIdx.x;
    if (idx >= total) return;
    float v = 0.f;
    for (int s = 0; s < S; s++) v += P[(size_t)s * total + idx];
    v += bias[idx % N];
    if (act == 1) {
        float x3 = v * v * v;
        v = 0.5f * v * (1.0f + tanhf(0.7978845608028654f * (v + 0.044715f * x3)));
    }
    dst[idx] = v;
}

// ---------------- attention: bulk-TMA, 2 linear stages + chunk-major K buffer ----------------
// Item w in [0,2048): b=w>>5, sp=w&31 -> 128 contiguous KV rows = 4 tiles of 32 rows (32KB).
// Stage is linear (TMA layout). V is read DIRECTLY from the stage (conflict-free).
// K alone is repacked chunk-major into kbuf with a quad-xor. At item end, the two
// row-group warps (rg=0/1) merge their partials in-CTA via a conflict-free
// column-major exchange in kbuf -> NPART=32.
#define TILE_R 32
#define TILE_F (TILE_R * 256)      // 8192 floats = 32KB
#define ATTN_T 256
#define XSTRIDE 132                // ull row stride for exchange (128 + 4 pad)

__global__ void __launch_bounds__(ATTN_T, 2) attn_kernel(
    const float* __restrict__ past, const float* __restrict__ qkv,
    const int* __restrict__ key_length,
    float* __restrict__ out_kv,
    float* __restrict__ m_part, float* __restrict__ l_part, float* __restrict__ acc_part)
{
    extern __shared__ float sm[];
    float* q_s  = sm;                         // 2048 floats
    float* kbuf = sm + 2048 + 16;             // 4096 floats (16KB), chunk-major K / merge buf
    float* stg0 = kbuf + 32 * 32 * 4;         // linear stage 0 (8192 floats)
    float* stg1 = stg0 + TILE_F;              // linear stage 1
    const uint32_t mb0 = s2u(sm + 2048);
    const uint32_t mb1 = mb0 + 8;

    const int tid = threadIdx.x, lane = tid & 31, warp = tid >> 5;
    const int hg = warp >> 1, rg = warp & 1, h0 = hg * 4;
    const int r16 = lane & 15, hs = lane >> 4;
    const int myrow = rg * 16 + r16;
    const int upd = key_length[0] - 1;

    if (tid == 0) { MBAR_INIT(mb0, 1); MBAR_INIT(mb1, 1); }
    __syncthreads();
    int ph0 = 0, ph1 = 0;

    for (int w = blockIdx.x; w < B_SZ * NITEM; w += 296) {
        const int b = w >> 5, sp = w & 31;
        const float* qb = qkv + (size_t)b * QKV_N;
        const float4* qnew = (const float4*)(qb + D_MODEL);
        const char* src_b = (const char*)past   + ((size_t)b * KV_LEN) * 1024;
        char*       dst_b = (char*)      out_kv + ((size_t)b * KV_LEN) * 1024;
        const int kvbase = sp * 128;

        __syncthreads();   // all threads done with q_s / kbuf from previous item

        for (int i = tid; i < 2048; i += ATTN_T)
            q_s[i] = qb[i] * 0.08838834764831845f;

        if (tid == 0) {
            BULK_WAIT_READ0();   // prior item's bulk stores have read the stages
            MBAR_EXPECT(mb0, TILE_F * 4);
            bulk_load(s2u(stg0), src_b + (size_t)kvbase * 1024, TILE_F * 4, mb0);
            MBAR_EXPECT(mb1, TILE_F * 4);
            bulk_load(s2u(stg1), src_b + (size_t)(kvbase + 32) * 1024, TILE_F * 4, mb1);
        }

        float m0 = -3.4e38f, m1 = -3.4e38f, l0 = 0.f, l1 = 0.f;
        ull acc0[4], acc1[4];
#pragma unroll
        for (int i = 0; i < 4; i++) { acc0[i] = 0ULL; acc1[i] = 0ULL; }

#pragma unroll 1
        for (int t = 0; t < 4; t++) {
            const int st = t & 1;
            float* s = st ? stg1 : stg0;
            if (st) { mbar_wait(mb1, ph1); ph1 ^= 1; }
            else    { mbar_wait(mb0, ph0); ph0 ^= 1; }
            const int kv0 = kvbase + t * 32;
            const bool hasupd = (upd >= kv0 && upd < kv0 + TILE_R);

            // rare: patch the updated KV row into the linear stage
            if (hasupd && tid < 64) {
                float4 val = qnew[tid];
                *(float4*)(s + (upd - kv0) * 256 + tid * 4) = val;
            }
            __syncthreads();   // patch visible; kbuf free (prev compute done)

            if (tid == 0) {
                if (hasupd) asm volatile("fence.proxy.async.shared::cta;" ::: "memory");
                bulk_store(dst_b + (size_t)kv0 * 1024, s2u(s), TILE_F * 4);
                BULK_COMMIT();
            }

            // repack K only: linear stage -> chunk-major kbuf (quad-xor)
#pragma unroll
            for (int li = 0; li < 4; li++) {
                int r = warp + li * 8;        // row 0..31
                float4 val = *(const float4*)(s + r * 256 + lane * 4);
                *(float4*)(kbuf + ((lane * 32 + (r ^ (lane & 7))) << 2)) = val;
            }
            __syncthreads();   // kbuf ready

            // ---- scores from kbuf (chunk-major): q broadcast, k 2-wf floor ----
            const float* qA = q_s + (h0 + 2 * hs) * HDIM;
            const float* qB = qA + HDIM;
            ull xa0 = 0ULL, xa1 = 0ULL, xb0 = 0ULL, xb1 = 0ULL;
#pragma unroll 8
            for (int d4 = 0; d4 < 32; d4++) {
                ulonglong2 k2 = *(const ulonglong2*)(kbuf + ((d4 * 32 + (myrow ^ (d4 & 7))) << 2));
                ulonglong2 qa2 = *(const ulonglong2*)(qA + d4 * 4);
                ulonglong2 qb2 = *(const ulonglong2*)(qB + d4 * 4);
                xa0 = ffma2(k2.x, qa2.x, xa0);
                xa1 = ffma2(k2.y, qa2.y, xa1);
                xb0 = ffma2(k2.x, qb2.x, xb0);
                xb1 = ffma2(k2.y, qb2.y, xb1);
            }
            ull xap = add2(xa0, xa1), xbp = add2(xb0, xb1);
            float xal, xah, xbl, xbh;
            upk2(xal, xah, xap);
            upk2(xbl, xbh, xbp);
            float xa = xal + xah, xb = xbl + xbh;

            float ta = xa, tb = xb;
#pragma unroll
            for (int o = 8; o; o >>= 1) {
                ta = fmaxf(ta, __shfl_xor_sync(0xffffffffu, ta, o));
                tb = fmaxf(tb, __shfl_xor_sync(0xffffffffu, tb, o));
            }
            float mna = fmaxf(m0, ta), mnb = fmaxf(m1, tb);
            float ca = __expf(m0 - mna), cb = __expf(m1 - mnb);
            float pa = __expf(xa - mna), pb = __expf(xb - mnb);
            float sa = pa, sb = pb;
#pragma unroll
            for (int o = 8; o; o >>= 1) {
                sa += __shfl_xor_sync(0xffffffffu, sa, o);
                sb += __shfl_xor_sync(0xffffffffu, sb, o);
            }
            l0 = l0 * ca + sa;  l1 = l1 * cb + sb;
            m0 = mna;           m1 = mnb;
            ull ca2 = pk2(ca, ca), cb2 = pk2(cb, cb);
#pragma unroll
            for (int i = 0; i < 4; i++) { acc0[i] = mul2(acc0[i], ca2); acc1[i] = mul2(acc1[i], cb2); }

            // ---- P @ V directly from the linear stage (conflict-free) ----
            const int rowbase = rg * 16;
#pragma unroll
            for (int r = 0; r < 16; r++) {
                int src = (lane & 16) | r;
                float p0 = __shfl_sync(0xffffffffu, pa, src);
                float p1 = __shfl_sync(0xffffffffu, pb, src);
                ull p02 = pk2(p0, p0), p12 = pk2(p1, p1);
                const float* vr = s + (rowbase + r) * 256 + 128;
                ulonglong2 v01 = *(const ulonglong2*)(vr + r16 * 4);
                ulonglong2 v23 = *(const ulonglong2*)(vr + 64 + r16 * 4);
                acc0[0] = ffma2(p02, v01.x, acc0[0]);
                acc0[1] = ffma2(p02, v01.y, acc0[1]);
                acc0[2] = ffma2(p02, v23.x, acc0[2]);
                acc0[3] = ffma2(p02, v23.y, acc0[3]);
                acc1[0] = ffma2(p12, v01.x, acc1[0]);
                acc1[1] = ffma2(p12, v01.y, acc1[1]);
                acc1[2] = ffma2(p12, v23.x, acc1[2]);
                acc1[3] = ffma2(p12, v23.y, acc1[3]);
            }
            __syncthreads();   // stage fully consumed (V reads + repack done)

            if (tid == 0 && t + 2 < 4) {
                BULK_WAIT_READ0();      // bulk store of this stage has read its data
                uint32_t mb = st ? mb1 : mb0;
                MBAR_EXPECT(mb, TILE_F * 4);
                bulk_load(s2u(s), src_b + (size_t)(kvbase + (t + 2) * 32) * 1024, TILE_F * 4, mb);
            }
        }

        // ---- in-CTA merge of rg=1 into rg=0 (conflict-free column-major exchange) ----
        ull*   xbuf  = (ull*)kbuf;                 // 8 rows x XSTRIDE ull
        float* mlbuf = kbuf + 2 * 8 * XSTRIDE;     // after xbuf (2112 ull -> float idx 2112*2? no: idx in floats)
        // xbuf occupies 8*XSTRIDE ull = 1056 ull = 2112 floats; place mlbuf at kbuf+2176
        mlbuf = kbuf + 2176;
        const int xidx = hg * 32 + lane;           // 0..127
        if (rg == 1) {
#pragma unroll
            for (int i = 0; i < 4; i++) {
                xbuf[i * XSTRIDE + xidx]       = acc0[i];
                xbuf[(4 + i) * XSTRIDE + xidx] = acc1[i];
            }
            float* ml = mlbuf + xidx * 4;
            ml[0] = m0; ml[1] = l0; ml[2] = m1; ml[3] = l1;
        }
        __syncthreads();
        if (rg == 0) {
            const float* ml = mlbuf + xidx * 4;
            float m0b = ml[0], l0b = ml[1], m1b = ml[2], l1b = ml[3];
            float mA = fmaxf(m0, m0b), mB = fmaxf(m1, m1b);
            float c0a = __expf(m0 - mA),  c0b = __expf(m0b - mA);
            float c1a = __expf(m1 - mB),  c1b = __expf(m1b - mB);
            l0 = l0 * c0a + l0b * c0b;
            l1 = l1 * c1a + l1b * c1b;
            ull c0a2 = pk2(c0a, c0a), c0b2 = pk2(c0b, c0b);
            ull c1a2 = pk2(c1a, c1a), c1b2 = pk2(c1b, c1b);
#pragma unroll
            for (int i = 0; i < 4; i++) {
                acc0[i] = add2(mul2(acc0[i], c0a2), mul2(xbuf[i * XSTRIDE + xidx],       c0b2));
                acc1[i] = add2(mul2(acc1[i], c1a2), mul2(xbuf[(4 + i) * XSTRIDE + xidx], c1b2));
            }
            const int ghA = h0 + 2 * hs, ghB = ghA + 1;
            const int phA = (b * N_HEAD + ghA) * NITEM + sp;
            const int phB = (b * N_HEAD + ghB) * NITEM + sp;
            if (r16 == 0) {
                m_part[phA] = mA; l_part[phA] = l0;
                m_part[phB] = mB; l_part[phB] = l1;
            }
            ull* dA = (ull*)(acc_part + (size_t)phA * HDIM);
            ull* dB = (ull*)(acc_part + (size_t)phB * HDIM);
            dA[r16 * 2]          = acc0[0];
            dA[r16 * 2 + 1]      = acc0[1];
            dA[32 + r16 * 2]     = acc0[2];
            dA[32 + r16 * 2 + 1] = acc0[3];
            dB[r16 * 2]          = acc1[0];
            dB[r16 * 2 + 1]      = acc1[1];
            dB[32 + r16 * 2]     = acc1[2];
            dB[32 + r16 * 2 + 1] = acc1[3];
        }
    }
}

// ---------------- combine split partial softmax results ----------------
__global__ void __launch_bounds__(128) attn_combine_kernel(
    const float* __restrict__ m_part, const float* __restrict__ l_part,
    const float* __restrict__ acc_part, float* __restrict__ attn_out)
{
    const int bh = blockIdx.x;
    const int d = threadIdx.x;
    float mm = -3.4e38f;
#pragma unroll 8
    for (int s = 0; s < NPART; s++) mm = fmaxf(mm, m_part[bh * NPART + s]);
    float L = 0.f, o = 0.f;
#pragma unroll 8
    for (int s = 0; s < NPART; s++) {
        float w = __expf(m_part[bh * NPART + s] - mm);
        L += l_part[bh * NPART + s] * w;
        o += acc_part[(size_t)(bh * NPART + s) * HDIM + d] * w;
    }
    int b = bh >> 4, h = bh & 15;
    attn_out[(size_t)b * D_MODEL + h * HDIM + d] = o / L;
}

// ---------------- launch ----------------
extern "C" void kernel_launch(void* const* d_in, const int* in_sizes, int n_in,
                              void* d_out, int out_size)
{
    const float* hidden = (const float*)d_in[0];
    const float* resid  = (const float*)d_in[1];
    const float* past   = (const float*)d_in[2];
    // d_in[3] = attention_mask (all-true; no-op)
    const int*   keylen = (const int*)d_in[4];
    const float* aaw = (const float*)d_in[5];
    const float* aab = (const float*)d_in[6];
    const float* apw = (const float*)d_in[7];
    const float* apb = (const float*)d_in[8];
    const float* l1w = (const float*)d_in[9];
    const float* l1b = (const float*)d_in[10];
    const float* l2w = (const float*)d_in[11];
    const float* l2b = (const float*)d_in[12];
    const float* mfw = (const float*)d_in[13];
    const float* mfb = (const float*)d_in[14];
    const float* mpw = (const float*)d_in[15];
    const float* mpb = (const float*)d_in[16];

    float* out     = (float*)d_out;
    float* out_hs  = out;
    float* out_res = out + B_SZ * D_MODEL;
    float* out_kv  = out + 2 * B_SZ * D_MODEL;

    float *res1, *hs1, *qkv, *attn, *tmp, *hs2, *mid, *part, *pm, *pl, *pacc;
    cudaGetSymbolAddress((void**)&res1, g_res1);
    cudaGetSymbolAddress((void**)&hs1,  g_hs1);
    cudaGetSymbolAddress((void**)&qkv,  g_qkv);
    cudaGetSymbolAddress((void**)&attn, g_attn);
    cudaGetSymbolAddress((void**)&tmp,  g_tmp);
    cudaGetSymbolAddress((void**)&hs2,  g_hs2);
    cudaGetSymbolAddress((void**)&mid,  g_mid);
    cudaGetSymbolAddress((void**)&part, g_part);
    cudaGetSymbolAddress((void**)&pm,   g_m);
    cudaGetSymbolAddress((void**)&pl,   g_l);
    cudaGetSymbolAddress((void**)&pacc, g_acc);

    const int attn_smem = (2048 + 16 + 32 * 32 * 4 + 2 * TILE_F) * sizeof(float);   // ~90 KB/CTA
    cudaFuncSetAttribute(attn_kernel, cudaFuncAttributeMaxDynamicSharedMemorySize, attn_smem);

    // 1) residual = hidden + residual ; hs1 = LN1(residual)
    add_ln_kernel<<<64, 256>>>(hidden, resid, l1w, l1b, res1, hs1);

    // 2) qkv = hs1 @ aaw + aab   (N=2304: 9 nb x 32 splits = 288 CTAs, klen 64)
    gemm_splitk_kernel<<<dim3(9, 32), 256>>>(hs1, aaw, part, 2048, 2304, 64);
    reduce_kernel<<<(B_SZ * QKV_N + 255) / 256, 256>>>(part, 32, B_SZ * QKV_N, QKV_N, aab, qkv, 0);

    // 3) attention + KV-cache update + fused layer_past copy-out
    attn_kernel<<<296, ATTN_T, attn_smem>>>(past, qkv, keylen, out_kv, pm, pl, pacc);
    attn_combine_kernel<<<B_SZ * N_HEAD, 128>>>(pm, pl, pacc, attn);

    // 4) proj = attn @ apw + apb  (N=2048: 8 nb x 32 splits = 256 CTAs, klen 64)
    gemm_splitk_kernel<<<dim3(8, 32), 256>>>(attn, apw, part, 2048, 2048, 64);
    reduce_kernel<<<(B_SZ * D_MODEL + 255) / 256, 256>>>(part, 32, B_SZ * D_MODEL, D_MODEL, apb, tmp, 0);

    // 5) residual2 = proj + residual1 (-> d_out) ; hs2 = LN2(residual2)
    add_ln_kernel<<<64, 256>>>(tmp, res1, l2w, l2b, out_res, hs2);

    // 6) mid = gelu(hs2 @ mfw + mfb)  (N=8192: 32 nb x 8 splits = 256 CTAs, klen 256)
    gemm_splitk_kernel<<<dim3(32, 8), 256>>>(hs2, mfw, part, 2048, 8192, 256);
    reduce_kernel<<<(B_SZ * FF_DIM + 255) / 256, 256>>>(part, 8, B_SZ * FF_DIM, FF_DIM, mfb, mid, 1);

    // 7) out_hs = mid @ mpw + mpb   (N=2048: 8 nb x 32 splits = 256 CTAs, klen 256)
    gemm_splitk_kernel<<<dim3(8, 32), 256>>>(mid, mpw, part, 8192, 2048, 256);
    reduce_kernel<<<(B_SZ * D_MODEL + 255) / 256, 256>>>(part, 32, B_SZ * D_MODEL, D_MODEL, mpb, out_hs, 0);
}

// round 14
// speedup vs baseline: 1.5996x; 1.0044x over previous
#include <cuda_runtime.h>
#include <cuda_bf16.h>
#include <cstdint>

#define D_MODEL 2048
#define B_SZ    64
#define KV_LEN  4096
#define N_HEAD  16
#define HDIM    128
#define QKV_N   2304
#define FF_DIM  8192
#define NITEM   32         // KV items per batch (128 rows each)
#define NPART   32         // one partial per item (rg merged in-CTA)

typedef unsigned long long ull;

// ---------------- scratch ----------------
__device__ float g_res1[B_SZ * D_MODEL];
__device__ float g_hs1 [B_SZ * D_MODEL];
__device__ float g_qkv [B_SZ * QKV_N];
__device__ float g_attn[B_SZ * D_MODEL];
__device__ float g_hs2 [B_SZ * D_MODEL];
__device__ float g_mid [B_SZ * FF_DIM];
__device__ float g_part[6291456];                   // split-K partials (fits 32*64*2304)
__device__ float g_m  [B_SZ * N_HEAD * NPART];
__device__ float g_l  [B_SZ * N_HEAD * NPART];
__device__ float g_acc[B_SZ * N_HEAD * NPART * HDIM];   // 16.8 MB

// ---------------- helpers ----------------
__device__ __forceinline__ float warp_sum(float v) {
#pragma unroll
    for (int o = 16; o; o >>= 1) v += __shfl_xor_sync(0xffffffffu, v, o);
    return v;
}
__device__ __forceinline__ ull pk2(float x, float y) {
    ull r;
    asm("mov.b64 %0, {%1,%2};" : "=l"(r) : "f"(x), "f"(y));
    return r;
}
__device__ __forceinline__ void upk2(float& x, float& y, ull p) {
    asm("mov.b64 {%0,%1}, %2;" : "=f"(x), "=f"(y) : "l"(p));
}
__device__ __forceinline__ ull ffma2(ull a, ull b, ull c) {
    ull d;
    asm("fma.rn.f32x2 %0, %1, %2, %3;" : "=l"(d) : "l"(a), "l"(b), "l"(c));
    return d;
}
__device__ __forceinline__ ull mul2(ull a, ull b) {
    ull d;
    asm("mul.rn.f32x2 %0, %1, %2;" : "=l"(d) : "l"(a), "l"(b));
    return d;
}
__device__ __forceinline__ ull add2(ull a, ull b) {
    ull d;
    asm("add.rn.f32x2 %0, %1, %2;" : "=l"(d) : "l"(a), "l"(b));
    return d;
}
__device__ __forceinline__ uint32_t s2u(const void* p) {
    return (uint32_t)__cvta_generic_to_shared(p);
}

// bulk TMA 1D copies
__device__ __forceinline__ void bulk_load(uint32_t smem_dst, const void* gmem_src,
                                          uint32_t bytes, uint32_t mbar) {
    asm volatile(
        "cp.async.bulk.shared::cluster.global.mbarrier::complete_tx::bytes [%0], [%1], %2, [%3];"
        :: "r"(smem_dst), "l"(gmem_src), "r"(bytes), "r"(mbar) : "memory");
}
__device__ __forceinline__ void bulk_store(void* gmem_dst, uint32_t smem_src, uint32_t bytes) {
    asm volatile(
        "cp.async.bulk.global.shared::cta.bulk_group [%0], [%1], %2;"
        :: "l"(gmem_dst), "r"(smem_src), "r"(bytes) : "memory");
}
#define BULK_COMMIT()      asm volatile("cp.async.bulk.commit_group;" ::: "memory")
#define BULK_WAIT_READ0()  asm volatile("cp.async.bulk.wait_group.read 0;" ::: "memory")
#define MBAR_INIT(a, n)    asm volatile("mbarrier.init.shared.b64 [%0], %1;" :: "r"(a), "r"(n) : "memory")
#define MBAR_EXPECT(a, b)  asm volatile("mbarrier.arrive.expect_tx.shared.b64 _, [%0], %1;" :: "r"(a), "r"(b) : "memory")

__device__ __forceinline__ void mbar_wait(uint32_t mbar, uint32_t parity) {
    uint32_t done;
    asm volatile(
        "{\n\t.reg .pred p;\n\t"
        "mbarrier.try_wait.parity.acquire.cta.shared::cta.b64 p, [%1], %2;\n\t"
        "selp.b32 %0, 1, 0, p;\n\t}"
        : "=r"(done) : "r"(mbar), "r"(parity) : "memory");
    if (!done) {
        asm volatile(
            "{\n\t.reg .pred P1;\n\t"
            "WL_%=:\n\t"
            "mbarrier.try_wait.parity.acquire.cta.shared::cta.b64 P1, [%0], %1, 0x989680;\n\t"
            "@P1 bra.uni WD_%=;\n\t"
            "bra.uni WL_%=;\n\t"
            "WD_%=:\n\t}"
            :: "r"(mbar), "r"(parity) : "memory");
    }
}

// ---------------- fused residual-add + LayerNorm (step 1) ----------------
__global__ void __launch_bounds__(256) add_ln_kernel(
    const float* __restrict__ a, const float* __restrict__ b,
    const float* __restrict__ w, const float* __restrict__ bias,
    float* __restrict__ res_out, float* __restrict__ ln_out)
{
    __shared__ float sh[33];
    const int row = blockIdx.x, tid = threadIdx.x;
    const int lane = tid & 31, wid = tid >> 5;

    const float4* a4 = (const float4*)(a + (size_t)row * D_MODEL);
    const float4* b4 = (const float4*)(b + (size_t)row * D_MODEL);
    float4 v0 = a4[tid], v1 = a4[tid + 256];
    float4 u0 = b4[tid], u1 = b4[tid + 256];
    v0.x += u0.x; v0.y += u0.y; v0.z += u0.z; v0.w += u0.w;
    v1.x += u1.x; v1.y += u1.y; v1.z += u1.z; v1.w += u1.w;

    float s = v0.x + v0.y + v0.z + v0.w + v1.x + v1.y + v1.z + v1.w;
    s = warp_sum(s);
    if (lane == 0) sh[wid] = s;
    __syncthreads();
    if (wid == 0) {
        float r = (lane < 8) ? sh[lane] : 0.f;
        r = warp_sum(r);
        if (lane == 0) sh[32] = r;
    }
    __syncthreads();
    const float mean = sh[32] * (1.0f / D_MODEL);

    float d0 = v0.x - mean, d1 = v0.y - mean, d2 = v0.z - mean, d3 = v0.w - mean;
    float d4 = v1.x - mean, d5 = v1.y - mean, d6 = v1.z - mean, d7 = v1.w - mean;
    float vs = d0*d0 + d1*d1 + d2*d2 + d3*d3 + d4*d4 + d5*d5 + d6*d6 + d7*d7;
    vs = warp_sum(vs);
    if (lane == 0) sh[wid] = vs;
    __syncthreads();
    if (wid == 0) {
        float r = (lane < 8) ? sh[lane] : 0.f;
        r = warp_sum(r);
        if (lane == 0) sh[32] = r;
    }
    __syncthreads();
    const float rstd = rsqrtf(sh[32] * (1.0f / D_MODEL) + 1e-5f);

    float4* ro = (float4*)(res_out + (size_t)row * D_MODEL);
    ro[tid] = v0; ro[tid + 256] = v1;

    const float4* w4 = (const float4*)w;
    const float4* c4 = (const float4*)bias;
    float4 W0 = w4[tid], W1 = w4[tid + 256], B0 = c4[tid], B1 = c4[tid + 256];
    float4 o0, o1;
    o0.x = d0 * rstd * W0.x + B0.x;  o0.y = d1 * rstd * W0.y + B0.y;
    o0.z = d2 * rstd * W0.z + B0.z;  o0.w = d3 * rstd * W0.w + B0.w;
    o1.x = d4 * rstd * W1.x + B1.x;  o1.y = d5 * rstd * W1.y + B1.y;
    o1.z = d6 * rstd * W1.z + B1.z;  o1.w = d7 * rstd * W1.w + B1.w;
    float4* lo = (float4*)(ln_out + (size_t)row * D_MODEL);
    lo[tid] = o0; lo[tid + 256] = o1;
}

// ---------------- fused split-K reduce + bias + residual-add + LayerNorm ----------------
// 1 block per row (64 rows), 512 threads, 1 float4 each (N = 2048).
__global__ void __launch_bounds__(512) freduce_ln_kernel(
    const float* __restrict__ P, int S,
    const float* __restrict__ bias, const float* __restrict__ resid,
    const float* __restrict__ w, const float* __restrict__ bv,
    float* __restrict__ res_out, float* __restrict__ ln_out)
{
    __shared__ float sh[17];
    const int row = blockIdx.x, tid = threadIdx.x;
    const int lane = tid & 31, wid = tid >> 5;
    const int stride4 = B_SZ * D_MODEL / 4;

    const float4* Pr = (const float4*)(P + (size_t)row * D_MODEL) + tid;
    float4 v = make_float4(0.f, 0.f, 0.f, 0.f);
#pragma unroll 4
    for (int s = 0; s < S; s++) {
        float4 p = Pr[(size_t)s * stride4];
        v.x += p.x; v.y += p.y; v.z += p.z; v.w += p.w;
    }
    float4 bb = ((const float4*)bias)[tid];
    float4 rr = ((const float4*)(resid + (size_t)row * D_MODEL))[tid];
    v.x += bb.x + rr.x; v.y += bb.y + rr.y;
    v.z += bb.z + rr.z; v.w += bb.w + rr.w;

    float s1 = warp_sum(v.x + v.y + v.z + v.w);
    if (lane == 0) sh[wid] = s1;
    __syncthreads();
    if (wid == 0) {
        float r = (lane < 16) ? sh[lane] : 0.f;
        r = warp_sum(r);
        if (lane == 0) sh[16] = r;
    }
    __syncthreads();
    const float mean = sh[16] * (1.0f / D_MODEL);

    float d0 = v.x - mean, d1 = v.y - mean, d2 = v.z - mean, d3 = v.w - mean;
    float vs = warp_sum(d0*d0 + d1*d1 + d2*d2 + d3*d3);
    if (lane == 0) sh[wid] = vs;
    __syncthreads();
    if (wid == 0) {
        float r = (lane < 16) ? sh[lane] : 0.f;
        r = warp_sum(r);
        if (lane == 0) sh[16] = r;
    }
    __syncthreads();
    const float rstd = rsqrtf(sh[16] * (1.0f / D_MODEL) + 1e-5f);

    ((float4*)(res_out + (size_t)row * D_MODEL))[tid] = v;
    float4 W = ((const float4*)w)[tid];
    float4 Bv = ((const float4*)bv)[tid];
    float4 o;
    o.x = d0 * rstd * W.x + Bv.x;  o.y = d1 * rstd * W.y + Bv.y;
    o.z = d2 * rstd * W.z + Bv.z;  o.w = d3 * rstd * W.w + Bv.w;
    ((float4*)(ln_out + (size_t)row * D_MODEL))[tid] = o;
}

// ---------------- split-K GEMM: BM=64, BN=256, BK=16, 2-stage smem, 1 sync/tile ----------------
__global__ void __launch_bounds__(256, 2) gemm_splitk_kernel(
    const float* __restrict__ A, const float* __restrict__ W,
    float* __restrict__ P, int K, int N, int klen)
{
    __shared__ ull   As2[2][16][66];
    __shared__ float Bs [2][16][256];
    const int n0 = blockIdx.x * 256;
    const int k0 = blockIdx.y * klen;
    const int tid = threadIdx.x;
    const int w = tid >> 5, lane = tid & 31;
    const int wm = w >> 2, wn = w & 3;
    const int lm = lane >> 3, ln = lane & 7;
    const int mbase = wm * 32 + lm * 8;
    const int nbase = wn * 64 + ln * 8;

    int am[4], ak[4], brow[4], bcol[4];
#pragma unroll
    for (int l = 0; l < 4; l++) {
        int ia = tid + l * 256;
        am[l] = ia >> 4; ak[l] = ia & 15;
        brow[l] = ia >> 6; bcol[l] = (ia & 63) * 4;
    }

    ull acc[8][4];
#pragma unroll
    for (int i = 0; i < 8; i++)
#pragma unroll
        for (int j = 0; j < 4; j++) acc[i][j] = 0ULL;

    float  a_r[4];
    float4 b_r[4];
#pragma unroll
    for (int l = 0; l < 4; l++) a_r[l] = A[(size_t)am[l] * K + k0 + ak[l]];
#pragma unroll
    for (int l = 0; l < 4; l++)
        b_r[l] = *(const float4*)&W[(size_t)(k0 + brow[l]) * N + n0 + bcol[l]];
#pragma unroll
    for (int l = 0; l < 4; l++) As2[0][ak[l]][am[l]] = pk2(a_r[l], a_r[l]);
#pragma unroll
    for (int l = 0; l < 4; l++) *(float4*)&Bs[0][brow[l]][bcol[l]] = b_r[l];

    const int nt = klen >> 4;
    for (int t = 0; t < nt; t++) {
        const int cur = t & 1;
        if (t + 1 < nt) {
            const int kb = k0 + (t + 1) * 16;
#pragma unroll
            for (int l = 0; l < 4; l++) a_r[l] = A[(size_t)am[l] * K + kb + ak[l]];
#pragma unroll
            for (int l = 0; l < 4; l++)
                b_r[l] = *(const float4*)&W[(size_t)(kb + brow[l]) * N + n0 + bcol[l]];
        }
        __syncthreads();

#pragma unroll
        for (int kk = 0; kk < 16; kk++) {
            // B pairs loaded directly as packed f32x2 (no repack movs)
            ulonglong2 bp0 = *(const ulonglong2*)&Bs[cur][kk][nbase];
            ulonglong2 bp1 = *(const ulonglong2*)&Bs[cur][kk][nbase + 4];
            ull bb0 = bp0.x, bb1 = bp0.y, bb2 = bp1.x, bb3 = bp1.y;
#pragma unroll
            for (int q = 0; q < 4; q++) {
                ulonglong2 aa = *(const ulonglong2*)&As2[cur][kk][mbase + 2 * q];
                acc[2*q][0]   = ffma2(aa.x, bb0, acc[2*q][0]);
                acc[2*q][1]   = ffma2(aa.x, bb1, acc[2*q][1]);
                acc[2*q][2]   = ffma2(aa.x, bb2, acc[2*q][2]);
                acc[2*q][3]   = ffma2(aa.x, bb3, acc[2*q][3]);
                acc[2*q+1][0] = ffma2(aa.y, bb0, acc[2*q+1][0]);
                acc[2*q+1][1] = ffma2(aa.y, bb1, acc[2*q+1][1]);
                acc[2*q+1][2] = ffma2(aa.y, bb2, acc[2*q+1][2]);
                acc[2*q+1][3] = ffma2(aa.y, bb3, acc[2*q+1][3]);
            }
        }

        if (t + 1 < nt) {
            const int nxt = cur ^ 1;
#pragma unroll
            for (int l = 0; l < 4; l++) As2[nxt][ak[l]][am[l]] = pk2(a_r[l], a_r[l]);
#pragma unroll
            for (int l = 0; l < 4; l++) *(float4*)&Bs[nxt][brow[l]][bcol[l]] = b_r[l];
        }
    }
    float* Pp = P + (size_t)blockIdx.y * 64 * (size_t)N;
#pragma unroll
    for (int i = 0; i < 8; i++) {
        size_t base = (size_t)(mbase + i) * N + n0 + nbase;
        *(ull*)&Pp[base]     = acc[i][0];
        *(ull*)&Pp[base + 2] = acc[i][1];
        *(ull*)&Pp[base + 4] = acc[i][2];
        *(ull*)&Pp[base + 6] = acc[i][3];
    }
}

// ---------------- split-K reduce + bias (+ optional tanh-gelu), float4 ----------------
__global__ void __launch_bounds__(256) reduce4_kernel(
    const float* __restrict__ P, int S, int total4, int N4,
    const float* __restrict__ bias, float* __restrict__ dst, int act)
{
    int idx = blockIdx.x * 256 + threadIdx.x;
    if (idx >= total4) return;
    const float4* P4 = (const float4*)P;
    float4 v = make_float4(0.f, 0.f, 0.f, 0.f);
    for (int s = 0; s < S; s++) {
        float4 p = P4[(size_t)s * total4 + idx];
        v.x += p.x; v.y += p.y; v.z += p.z; v.w += p.w;
    }
    float4 bb = ((const float4*)bias)[idx % N4];
    v.x += bb.x; v.y += bb.y; v.z += bb.z; v.w += bb.w;
    if (act == 1) {
        float* f = (float*)&v;
#pragma unroll
        for (int j = 0; j < 4; j++) {
            float x = f[j];
            float x3 = x * x * x;
            f[j] = 0.5f * x * (1.0f + tanhf(0.7978845608028654f * (x + 0.044715f * x3)));
        }
    }
    ((float4*)dst)[idx] = v;
}

// ---------------- attention: bulk-TMA, 2 linear stages + chunk-major K buffer ----------------
#define TILE_R 32
#define TILE_F (TILE_R * 256)      // 8192 floats = 32KB
#define ATTN_T 256
#define XSTRIDE 132                // ull row stride for exchange (128 + 4 pad)

__global__ void __launch_bounds__(ATTN_T, 2) attn_kernel(
    const float* __restrict__ past, const float* __restrict__ qkv,
    const int* __restrict__ key_length,
    float* __restrict__ out_kv,
    float* __restrict__ m_part, float* __restrict__ l_part, float* __restrict__ acc_part)
{
    extern __shared__ float sm[];
    float* q_s  = sm;                         // 2048 floats
    float* kbuf = sm + 2048 + 16;             // 4096 floats (16KB), chunk-major K / merge buf
    float* stg0 = kbuf + 32 * 32 * 4;         // linear stage 0 (8192 floats)
    float* stg1 = stg0 + TILE_F;              // linear stage 1
    const uint32_t mb0 = s2u(sm + 2048);
    const uint32_t mb1 = mb0 + 8;

    const int tid = threadIdx.x, lane = tid & 31, warp = tid >> 5;
    const int hg = warp >> 1, rg = warp & 1, h0 = hg * 4;
    const int r16 = lane & 15, hs = lane >> 4;
    const int myrow = rg * 16 + r16;
    const int upd = key_length[0] - 1;

    if (tid == 0) { MBAR_INIT(mb0, 1); MBAR_INIT(mb1, 1); }
    __syncthreads();
    int ph0 = 0, ph1 = 0;

    for (int w = blockIdx.x; w < B_SZ * NITEM; w += 296) {
        const int b = w >> 5, sp = w & 31;
        const float* qb = qkv + (size_t)b * QKV_N;
        const float4* qnew = (const float4*)(qb + D_MODEL);
        const char* src_b = (const char*)past   + ((size_t)b * KV_LEN) * 1024;
        char*       dst_b = (char*)      out_kv + ((size_t)b * KV_LEN) * 1024;
        const int kvbase = sp * 128;

        __syncthreads();   // all threads done with q_s / kbuf from previous item

        for (int i = tid; i < 2048; i += ATTN_T)
            q_s[i] = qb[i] * 0.08838834764831845f;

        if (tid == 0) {
            BULK_WAIT_READ0();   // prior item's bulk stores have read the stages
            MBAR_EXPECT(mb0, TILE_F * 4);
            bulk_load(s2u(stg0), src_b + (size_t)kvbase * 1024, TILE_F * 4, mb0);
            MBAR_EXPECT(mb1, TILE_F * 4);
            bulk_load(s2u(stg1), src_b + (size_t)(kvbase + 32) * 1024, TILE_F * 4, mb1);
        }

        float m0 = -3.4e38f, m1 = -3.4e38f, l0 = 0.f, l1 = 0.f;
        ull acc0[4], acc1[4];
#pragma unroll
        for (int i = 0; i < 4; i++) { acc0[i] = 0ULL; acc1[i] = 0ULL; }

#pragma unroll 1
        for (int t = 0; t < 4; t++) {
            const int st = t & 1;
            float* s = st ? stg1 : stg0;
            if (st) { mbar_wait(mb1, ph1); ph1 ^= 1; }
            else    { mbar_wait(mb0, ph0); ph0 ^= 1; }
            const int kv0 = kvbase + t * 32;
            const bool hasupd = (upd >= kv0 && upd < kv0 + TILE_R);

            // rare: patch the updated KV row into the linear stage
            if (hasupd && tid < 64) {
                float4 val = qnew[tid];
                *(float4*)(s + (upd - kv0) * 256 + tid * 4) = val;
            }
            __syncthreads();   // patch visible; kbuf free (prev compute done)

            if (tid == 0) {
                if (hasupd) asm volatile("fence.proxy.async.shared::cta;" ::: "memory");
                bulk_store(dst_b + (size_t)kv0 * 1024, s2u(s), TILE_F * 4);
                BULK_COMMIT();
            }

            // repack K only: linear stage -> chunk-major kbuf (quad-xor)
#pragma unroll
            for (int li = 0; li < 4; li++) {
                int r = warp + li * 8;        // row 0..31
                float4 val = *(const float4*)(s + r * 256 + lane * 4);
                *(float4*)(kbuf + ((lane * 32 + (r ^ (lane & 7))) << 2)) = val;
            }
            __syncthreads();   // kbuf ready

            // ---- scores from kbuf (chunk-major): q broadcast, k 2-wf floor ----
            const float* qA = q_s + (h0 + 2 * hs) * HDIM;
            const float* qB = qA + HDIM;
            ull xa0 = 0ULL, xa1 = 0ULL, xb0 = 0ULL, xb1 = 0ULL;
#pragma unroll 8
            for (int d4 = 0; d4 < 32; d4++) {
                ulonglong2 k2 = *(const ulonglong2*)(kbuf + ((d4 * 32 + (myrow ^ (d4 & 7))) << 2));
                ulonglong2 qa2 = *(const ulonglong2*)(qA + d4 * 4);
                ulonglong2 qb2 = *(const ulonglong2*)(qB + d4 * 4);
                xa0 = ffma2(k2.x, qa2.x, xa0);
                xa1 = ffma2(k2.y, qa2.y, xa1);
                xb0 = ffma2(k2.x, qb2.x, xb0);
                xb1 = ffma2(k2.y, qb2.y, xb1);
            }
            ull xap = add2(xa0, xa1), xbp = add2(xb0, xb1);
            float xal, xah, xbl, xbh;
            upk2(xal, xah, xap);
            upk2(xbl, xbh, xbp);
            float xa = xal + xah, xb = xbl + xbh;

            float ta = xa, tb = xb;
#pragma unroll
            for (int o = 8; o; o >>= 1) {
                ta = fmaxf(ta, __shfl_xor_sync(0xffffffffu, ta, o));
                tb = fmaxf(tb, __shfl_xor_sync(0xffffffffu, tb, o));
            }
            float mna = fmaxf(m0, ta), mnb = fmaxf(m1, tb);
            float ca = __expf(m0 - mna), cb = __expf(m1 - mnb);
            float pa = __expf(xa - mna), pb = __expf(xb - mnb);
            float sa = pa, sb = pb;
#pragma unroll
            for (int o = 8; o; o >>= 1) {
                sa += __shfl_xor_sync(0xffffffffu, sa, o);
                sb += __shfl_xor_sync(0xffffffffu, sb, o);
            }
            l0 = l0 * ca + sa;  l1 = l1 * cb + sb;
            m0 = mna;           m1 = mnb;
            ull ca2 = pk2(ca, ca), cb2 = pk2(cb, cb);
#pragma unroll
            for (int i = 0; i < 4; i++) { acc0[i] = mul2(acc0[i], ca2); acc1[i] = mul2(acc1[i], cb2); }

            // ---- P @ V directly from the linear stage (conflict-free) ----
            const int rowbase = rg * 16;
#pragma unroll
            for (int r = 0; r < 16; r++) {
                int src = (lane & 16) | r;
                float p0 = __shfl_sync(0xffffffffu, pa, src);
                float p1 = __shfl_sync(0xffffffffu, pb, src);
                ull p02 = pk2(p0, p0), p12 = pk2(p1, p1);
                const float* vr = s + (rowbase + r) * 256 + 128;
                ulonglong2 v01 = *(const ulonglong2*)(vr + r16 * 4);
                ulonglong2 v23 = *(const ulonglong2*)(vr + 64 + r16 * 4);
                acc0[0] = ffma2(p02, v01.x, acc0[0]);
                acc0[1] = ffma2(p02, v01.y, acc0[1]);
                acc0[2] = ffma2(p02, v23.x, acc0[2]);
                acc0[3] = ffma2(p02, v23.y, acc0[3]);
                acc1[0] = ffma2(p12, v01.x, acc1[0]);
                acc1[1] = ffma2(p12, v01.y, acc1[1]);
                acc1[2] = ffma2(p12, v23.x, acc1[2]);
                acc1[3] = ffma2(p12, v23.y, acc1[3]);
            }
            __syncthreads();   // stage fully consumed (V reads + repack done)

            if (tid == 0 && t + 2 < 4) {
                BULK_WAIT_READ0();      // bulk store of this stage has read its data
                uint32_t mb = st ? mb1 : mb0;
                MBAR_EXPECT(mb, TILE_F * 4);
                bulk_load(s2u(s), src_b + (size_t)(kvbase + (t + 2) * 32) * 1024, TILE_F * 4, mb);
            }
        }

        // ---- in-CTA merge of rg=1 into rg=0 (conflict-free column-major exchange) ----
        ull*   xbuf  = (ull*)kbuf;                 // 8 rows x XSTRIDE ull
        float* mlbuf = kbuf + 2176;                // after xbuf (1056 ull = 2112 floats)
        const int xidx = hg * 32 + lane;           // 0..127
        if (rg == 1) {
#pragma unroll
            for (int i = 0; i < 4; i++) {
                xbuf[i * XSTRIDE + xidx]       = acc0[i];
                xbuf[(4 + i) * XSTRIDE + xidx] = acc1[i];
            }
            float* ml = mlbuf + xidx * 4;
            ml[0] = m0; ml[1] = l0; ml[2] = m1; ml[3] = l1;
        }
        __syncthreads();
        if (rg == 0) {
            const float* ml = mlbuf + xidx * 4;
            float m0b = ml[0], l0b = ml[1], m1b = ml[2], l1b = ml[3];
            float mA = fmaxf(m0, m0b), mB = fmaxf(m1, m1b);
            float c0a = __expf(m0 - mA),  c0b = __expf(m0b - mA);
            float c1a = __expf(m1 - mB),  c1b = __expf(m1b - mB);
            l0 = l0 * c0a + l0b * c0b;
            l1 = l1 * c1a + l1b * c1b;
            ull c0a2 = pk2(c0a, c0a), c0b2 = pk2(c0b, c0b);
            ull c1a2 = pk2(c1a, c1a), c1b2 = pk2(c1b, c1b);
#pragma unroll
            for (int i = 0; i < 4; i++) {
                acc0[i] = add2(mul2(acc0[i], c0a2), mul2(xbuf[i * XSTRIDE + xidx],       c0b2));
                acc1[i] = add2(mul2(acc1[i], c1a2), mul2(xbuf[(4 + i) * XSTRIDE + xidx], c1b2));
            }
            const int ghA = h0 + 2 * hs, ghB = ghA + 1;
            const int phA = (b * N_HEAD + ghA) * NITEM + sp;
            const int phB = (b * N_HEAD + ghB) * NITEM + sp;
            if (r16 == 0) {
                m_part[phA] = mA; l_part[phA] = l0;
                m_part[phB] = mB; l_part[phB] = l1;
            }
            ull* dA = (ull*)(acc_part + (size_t)phA * HDIM);
            ull* dB = (ull*)(acc_part + (size_t)phB * HDIM);
            dA[r16 * 2]          = acc0[0];
            dA[r16 * 2 + 1]      = acc0[1];
            dA[32 + r16 * 2]     = acc0[2];
            dA[32 + r16 * 2 + 1] = acc0[3];
            dB[r16 * 2]          = acc1[0];
            dB[r16 * 2 + 1]      = acc1[1];
            dB[32 + r16 * 2]     = acc1[2];
            dB[32 + r16 * 2 + 1] = acc1[3];
        }
    }
}

// ---------------- combine split partial softmax results ----------------
__global__ void __launch_bounds__(128) attn_combine_kernel(
    const float* __restrict__ m_part, const float* __restrict__ l_part,
    const float* __restrict__ acc_part, float* __restrict__ attn_out)
{
    const int bh = blockIdx.x;
    const int d = threadIdx.x;
    float mm = -3.4e38f;
#pragma unroll 8
    for (int s = 0; s < NPART; s++) mm = fmaxf(mm, m_part[bh * NPART + s]);
    float L = 0.f, o = 0.f;
#pragma unroll 8
    for (int s = 0; s < NPART; s++) {
        float w = __expf(m_part[bh * NPART + s] - mm);
        L += l_part[bh * NPART + s] * w;
        o += acc_part[(size_t)(bh * NPART + s) * HDIM + d] * w;
    }
    int b = bh >> 4, h = bh & 15;
    attn_out[(size_t)b * D_MODEL + h * HDIM + d] = o / L;
}

// ---------------- launch ----------------
extern "C" void kernel_launch(void* const* d_in, const int* in_sizes, int n_in,
                              void* d_out, int out_size)
{
    const float* hidden = (const float*)d_in[0];
    const float* resid  = (const float*)d_in[1];
    const float* past   = (const float*)d_in[2];
    // d_in[3] = attention_mask (all-true; no-op)
    const int*   keylen = (const int*)d_in[4];
    const float* aaw = (const float*)d_in[5];
    const float* aab = (const float*)d_in[6];
    const float* apw = (const float*)d_in[7];
    const float* apb = (const float*)d_in[8];
    const float* l1w = (const float*)d_in[9];
    const float* l1b = (const float*)d_in[10];
    const float* l2w = (const float*)d_in[11];
    const float* l2b = (const float*)d_in[12];
    const float* mfw = (const float*)d_in[13];
    const float* mfb = (const float*)d_in[14];
    const float* mpw = (const float*)d_in[15];
    const float* mpb = (const float*)d_in[16];

    float* out     = (float*)d_out;
    float* out_hs  = out;
    float* out_res = out + B_SZ * D_MODEL;
    float* out_kv  = out + 2 * B_SZ * D_MODEL;

    float *res1, *hs1, *qkv, *attn, *hs2, *mid, *part, *pm, *pl, *pacc;
    cudaGetSymbolAddress((void**)&res1, g_res1);
    cudaGetSymbolAddress((void**)&hs1,  g_hs1);
    cudaGetSymbolAddress((void**)&qkv,  g_qkv);
    cudaGetSymbolAddress((void**)&attn, g_attn);
    cudaGetSymbolAddress((void**)&hs2,  g_hs2);
    cudaGetSymbolAddress((void**)&mid,  g_mid);
    cudaGetSymbolAddress((void**)&part, g_part);
    cudaGetSymbolAddress((void**)&pm,   g_m);
    cudaGetSymbolAddress((void**)&pl,   g_l);
    cudaGetSymbolAddress((void**)&pacc, g_acc);

    const int attn_smem = (2048 + 16 + 32 * 32 * 4 + 2 * TILE_F) * sizeof(float);   // ~90 KB/CTA
    cudaFuncSetAttribute(attn_kernel, cudaFuncAttributeMaxDynamicSharedMemorySize, attn_smem);

    // 1) residual = hidden + residual ; hs1 = LN1(residual)
    add_ln_kernel<<<64, 256>>>(hidden, resid, l1w, l1b, res1, hs1);

    // 2) qkv = hs1 @ aaw + aab   (N=2304: 9 nb x 32 splits = 288 CTAs, klen 64)
    gemm_splitk_kernel<<<dim3(9, 32), 256>>>(hs1, aaw, part, 2048, 2304, 64);
    reduce4_kernel<<<(B_SZ * QKV_N / 4 + 255) / 256, 256>>>(part, 32, B_SZ * QKV_N / 4, QKV_N / 4, aab, qkv, 0);

    // 3) attention + KV-cache update + fused layer_past copy-out
    attn_kernel<<<296, ATTN_T, attn_smem>>>(past, qkv, keylen, out_kv, pm, pl, pacc);
    attn_combine_kernel<<<B_SZ * N_HEAD, 128>>>(pm, pl, pacc, attn);

    // 4+5) proj reduce + bias + residual-add + LN2 (fused; -> out_res, hs2)
    gemm_splitk_kernel<<<dim3(8, 32), 256>>>(attn, apw, part, 2048, 2048, 64);
    freduce_ln_kernel<<<64, 512>>>(part, 32, apb, res1, l2w, l2b, out_res, hs2);

    // 6) mid = gelu(hs2 @ mfw + mfb)  (N=8192: 32 nb x 8 splits = 256 CTAs, klen 256)
    gemm_splitk_kernel<<<dim3(32, 8), 256>>>(hs2, mfw, part, 2048, 8192, 256);
    reduce4_kernel<<<(B_SZ * FF_DIM / 4 + 255) / 256, 256>>>(part, 8, B_SZ * FF_DIM / 4, FF_DIM / 4, mfb, mid, 1);

    // 7) out_hs = mid @ mpw + mpb   (N=2048: 8 nb x 32 splits = 256 CTAs, klen 256)
    gemm_splitk_kernel<<<dim3(8, 32), 256>>>(mid, mpw, part, 8192, 2048, 256);
    reduce4_kernel<<<(B_SZ * D_MODEL / 4 + 255) / 256, 256>>>(part, 32, B_SZ * D_MODEL / 4, D_MODEL / 4, mpb, out_hs, 0);
}

// round 15
// speedup vs baseline: 1.6153x; 1.0098x over previous
#include <cuda_runtime.h>
#include <cuda_bf16.h>
#include <cstdint>

#define D_MODEL 2048
#define B_SZ    64
#define KV_LEN  4096
#define N_HEAD  16
#define HDIM    128
#define QKV_N   2304
#define FF_DIM  8192
#define NITEM   32         // KV items per batch (128 rows each)
#define NPART   32         // one partial per item (rg merged in-CTA)

typedef unsigned long long ull;

// ---------------- scratch ----------------
__device__ float g_res1[B_SZ * D_MODEL];
__device__ float g_hs1 [B_SZ * D_MODEL];
__device__ float g_qkv [B_SZ * QKV_N];
__device__ float g_attn[B_SZ * D_MODEL];
__device__ float g_hs2 [B_SZ * D_MODEL];
__device__ float g_mid [B_SZ * FF_DIM];
__device__ float g_part[6291456];                   // split-K partials (fits 32*64*2304)
__device__ float g_m  [B_SZ * N_HEAD * NPART];
__device__ float g_l  [B_SZ * N_HEAD * NPART];
__device__ float g_acc[B_SZ * N_HEAD * NPART * HDIM];   // 16.8 MB

// ---------------- helpers ----------------
__device__ __forceinline__ float warp_sum(float v) {
#pragma unroll
    for (int o = 16; o; o >>= 1) v += __shfl_xor_sync(0xffffffffu, v, o);
    return v;
}
__device__ __forceinline__ ull pk2(float x, float y) {
    ull r;
    asm("mov.b64 %0, {%1,%2};" : "=l"(r) : "f"(x), "f"(y));
    return r;
}
__device__ __forceinline__ void upk2(float& x, float& y, ull p) {
    asm("mov.b64 {%0,%1}, %2;" : "=f"(x), "=f"(y) : "l"(p));
}
__device__ __forceinline__ ull ffma2(ull a, ull b, ull c) {
    ull d;
    asm("fma.rn.f32x2 %0, %1, %2, %3;" : "=l"(d) : "l"(a), "l"(b), "l"(c));
    return d;
}
__device__ __forceinline__ ull mul2(ull a, ull b) {
    ull d;
    asm("mul.rn.f32x2 %0, %1, %2;" : "=l"(d) : "l"(a), "l"(b));
    return d;
}
__device__ __forceinline__ ull add2(ull a, ull b) {
    ull d;
    asm("add.rn.f32x2 %0, %1, %2;" : "=l"(d) : "l"(a), "l"(b));
    return d;
}
__device__ __forceinline__ uint32_t s2u(const void* p) {
    return (uint32_t)__cvta_generic_to_shared(p);
}

// bulk TMA 1D copies
__device__ __forceinline__ void bulk_load(uint32_t smem_dst, const void* gmem_src,
                                          uint32_t bytes, uint32_t mbar) {
    asm volatile(
        "cp.async.bulk.shared::cluster.global.mbarrier::complete_tx::bytes [%0], [%1], %2, [%3];"
        :: "r"(smem_dst), "l"(gmem_src), "r"(bytes), "r"(mbar) : "memory");
}
__device__ __forceinline__ void bulk_store(void* gmem_dst, uint32_t smem_src, uint32_t bytes) {
    asm volatile(
        "cp.async.bulk.global.shared::cta.bulk_group [%0], [%1], %2;"
        :: "l"(gmem_dst), "r"(smem_src), "r"(bytes) : "memory");
}
#define BULK_COMMIT()      asm volatile("cp.async.bulk.commit_group;" ::: "memory")
#define BULK_WAIT_READ0()  asm volatile("cp.async.bulk.wait_group.read 0;" ::: "memory")
#define MBAR_INIT(a, n)    asm volatile("mbarrier.init.shared.b64 [%0], %1;" :: "r"(a), "r"(n) : "memory")
#define MBAR_EXPECT(a, b)  asm volatile("mbarrier.arrive.expect_tx.shared.b64 _, [%0], %1;" :: "r"(a), "r"(b) : "memory")

__device__ __forceinline__ void mbar_wait(uint32_t mbar, uint32_t parity) {
    uint32_t done;
    asm volatile(
        "{\n\t.reg .pred p;\n\t"
        "mbarrier.try_wait.parity.acquire.cta.shared::cta.b64 p, [%1], %2;\n\t"
        "selp.b32 %0, 1, 0, p;\n\t}"
        : "=r"(done) : "r"(mbar), "r"(parity) : "memory");
    if (!done) {
        asm volatile(
            "{\n\t.reg .pred P1;\n\t"
            "WL_%=:\n\t"
            "mbarrier.try_wait.parity.acquire.cta.shared::cta.b64 P1, [%0], %1, 0x989680;\n\t"
            "@P1 bra.uni WD_%=;\n\t"
            "bra.uni WL_%=;\n\t"
            "WD_%=:\n\t}"
            :: "r"(mbar), "r"(parity) : "memory");
    }
}

// ---------------- fused residual-add + LayerNorm (step 1) ----------------
__global__ void __launch_bounds__(256) add_ln_kernel(
    const float* __restrict__ a, const float* __restrict__ b,
    const float* __restrict__ w, const float* __restrict__ bias,
    float* __restrict__ res_out, float* __restrict__ ln_out)
{
    __shared__ float sh[33];
    const int row = blockIdx.x, tid = threadIdx.x;
    const int lane = tid & 31, wid = tid >> 5;

    const float4* a4 = (const float4*)(a + (size_t)row * D_MODEL);
    const float4* b4 = (const float4*)(b + (size_t)row * D_MODEL);
    float4 v0 = a4[tid], v1 = a4[tid + 256];
    float4 u0 = b4[tid], u1 = b4[tid + 256];
    v0.x += u0.x; v0.y += u0.y; v0.z += u0.z; v0.w += u0.w;
    v1.x += u1.x; v1.y += u1.y; v1.z += u1.z; v1.w += u1.w;

    float s = v0.x + v0.y + v0.z + v0.w + v1.x + v1.y + v1.z + v1.w;
    s = warp_sum(s);
    if (lane == 0) sh[wid] = s;
    __syncthreads();
    if (wid == 0) {
        float r = (lane < 8) ? sh[lane] : 0.f;
        r = warp_sum(r);
        if (lane == 0) sh[32] = r;
    }
    __syncthreads();
    const float mean = sh[32] * (1.0f / D_MODEL);

    float d0 = v0.x - mean, d1 = v0.y - mean, d2 = v0.z - mean, d3 = v0.w - mean;
    float d4 = v1.x - mean, d5 = v1.y - mean, d6 = v1.z - mean, d7 = v1.w - mean;
    float vs = d0*d0 + d1*d1 + d2*d2 + d3*d3 + d4*d4 + d5*d5 + d6*d6 + d7*d7;
    vs = warp_sum(vs);
    if (lane == 0) sh[wid] = vs;
    __syncthreads();
    if (wid == 0) {
        float r = (lane < 8) ? sh[lane] : 0.f;
        r = warp_sum(r);
        if (lane == 0) sh[32] = r;
    }
    __syncthreads();
    const float rstd = rsqrtf(sh[32] * (1.0f / D_MODEL) + 1e-5f);

    float4* ro = (float4*)(res_out + (size_t)row * D_MODEL);
    ro[tid] = v0; ro[tid + 256] = v1;

    const float4* w4 = (const float4*)w;
    const float4* c4 = (const float4*)bias;
    float4 W0 = w4[tid], W1 = w4[tid + 256], B0 = c4[tid], B1 = c4[tid + 256];
    float4 o0, o1;
    o0.x = d0 * rstd * W0.x + B0.x;  o0.y = d1 * rstd * W0.y + B0.y;
    o0.z = d2 * rstd * W0.z + B0.z;  o0.w = d3 * rstd * W0.w + B0.w;
    o1.x = d4 * rstd * W1.x + B1.x;  o1.y = d5 * rstd * W1.y + B1.y;
    o1.z = d6 * rstd * W1.z + B1.z;  o1.w = d7 * rstd * W1.w + B1.w;
    float4* lo = (float4*)(ln_out + (size_t)row * D_MODEL);
    lo[tid] = o0; lo[tid + 256] = o1;
}

// ---------------- fused split-K reduce + bias + residual-add + LayerNorm ----------------
__global__ void __launch_bounds__(512) freduce_ln_kernel(
    const float* __restrict__ P, int S,
    const float* __restrict__ bias, const float* __restrict__ resid,
    const float* __restrict__ w, const float* __restrict__ bv,
    float* __restrict__ res_out, float* __restrict__ ln_out)
{
    __shared__ float sh[17];
    const int row = blockIdx.x, tid = threadIdx.x;
    const int lane = tid & 31, wid = tid >> 5;
    const int stride4 = B_SZ * D_MODEL / 4;

    const float4* Pr = (const float4*)(P + (size_t)row * D_MODEL) + tid;
    float4 v = make_float4(0.f, 0.f, 0.f, 0.f);
#pragma unroll 4
    for (int s = 0; s < S; s++) {
        float4 p = Pr[(size_t)s * stride4];
        v.x += p.x; v.y += p.y; v.z += p.z; v.w += p.w;
    }
    float4 bb = ((const float4*)bias)[tid];
    float4 rr = ((const float4*)(resid + (size_t)row * D_MODEL))[tid];
    v.x += bb.x + rr.x; v.y += bb.y + rr.y;
    v.z += bb.z + rr.z; v.w += bb.w + rr.w;

    float s1 = warp_sum(v.x + v.y + v.z + v.w);
    if (lane == 0) sh[wid] = s1;
    __syncthreads();
    if (wid == 0) {
        float r = (lane < 16) ? sh[lane] : 0.f;
        r = warp_sum(r);
        if (lane == 0) sh[16] = r;
    }
    __syncthreads();
    const float mean = sh[16] * (1.0f / D_MODEL);

    float d0 = v.x - mean, d1 = v.y - mean, d2 = v.z - mean, d3 = v.w - mean;
    float vs = warp_sum(d0*d0 + d1*d1 + d2*d2 + d3*d3);
    if (lane == 0) sh[wid] = vs;
    __syncthreads();
    if (wid == 0) {
        float r = (lane < 16) ? sh[lane] : 0.f;
        r = warp_sum(r);
        if (lane == 0) sh[16] = r;
    }
    __syncthreads();
    const float rstd = rsqrtf(sh[16] * (1.0f / D_MODEL) + 1e-5f);

    ((float4*)(res_out + (size_t)row * D_MODEL))[tid] = v;
    float4 W = ((const float4*)w)[tid];
    float4 Bv = ((const float4*)bv)[tid];
    float4 o;
    o.x = d0 * rstd * W.x + Bv.x;  o.y = d1 * rstd * W.y + Bv.y;
    o.z = d2 * rstd * W.z + Bv.z;  o.w = d3 * rstd * W.w + Bv.w;
    ((float4*)(ln_out + (size_t)row * D_MODEL))[tid] = o;
}

// ---------------- split-K GEMM: BM=64, BN=256, BK=16, 2-stage smem, 1 sync/tile ----------------
__global__ void __launch_bounds__(256, 2) gemm_splitk_kernel(
    const float* __restrict__ A, const float* __restrict__ W,
    float* __restrict__ P, int K, int N, int klen)
{
    __shared__ ull   As2[2][16][66];
    __shared__ float Bs [2][16][256];
    const int n0 = blockIdx.x * 256;
    const int k0 = blockIdx.y * klen;
    const int tid = threadIdx.x;
    const int w = tid >> 5, lane = tid & 31;
    const int wm = w >> 2, wn = w & 3;
    const int lm = lane >> 3, ln = lane & 7;
    const int mbase = wm * 32 + lm * 8;
    const int nbase = wn * 64 + ln * 8;

    int am[4], ak[4], brow[4], bcol[4];
#pragma unroll
    for (int l = 0; l < 4; l++) {
        int ia = tid + l * 256;
        am[l] = ia >> 4; ak[l] = ia & 15;
        brow[l] = ia >> 6; bcol[l] = (ia & 63) * 4;
    }

    ull acc[8][4];
#pragma unroll
    for (int i = 0; i < 8; i++)
#pragma unroll
        for (int j = 0; j < 4; j++) acc[i][j] = 0ULL;

    float  a_r[4];
    float4 b_r[4];
#pragma unroll
    for (int l = 0; l < 4; l++) a_r[l] = A[(size_t)am[l] * K + k0 + ak[l]];
#pragma unroll
    for (int l = 0; l < 4; l++)
        b_r[l] = *(const float4*)&W[(size_t)(k0 + brow[l]) * N + n0 + bcol[l]];
#pragma unroll
    for (int l = 0; l < 4; l++) As2[0][ak[l]][am[l]] = pk2(a_r[l], a_r[l]);
#pragma unroll
    for (int l = 0; l < 4; l++) *(float4*)&Bs[0][brow[l]][bcol[l]] = b_r[l];

    const int nt = klen >> 4;
    for (int t = 0; t < nt; t++) {
        const int cur = t & 1;
        if (t + 1 < nt) {
            const int kb = k0 + (t + 1) * 16;
#pragma unroll
            for (int l = 0; l < 4; l++) a_r[l] = A[(size_t)am[l] * K + kb + ak[l]];
#pragma unroll
            for (int l = 0; l < 4; l++)
                b_r[l] = *(const float4*)&W[(size_t)(kb + brow[l]) * N + n0 + bcol[l]];
        }
        __syncthreads();

#pragma unroll
        for (int kk = 0; kk < 16; kk++) {
            ulonglong2 bp0 = *(const ulonglong2*)&Bs[cur][kk][nbase];
            ulonglong2 bp1 = *(const ulonglong2*)&Bs[cur][kk][nbase + 4];
            ull bb0 = bp0.x, bb1 = bp0.y, bb2 = bp1.x, bb3 = bp1.y;
#pragma unroll
            for (int q = 0; q < 4; q++) {
                ulonglong2 aa = *(const ulonglong2*)&As2[cur][kk][mbase + 2 * q];
                acc[2*q][0]   = ffma2(aa.x, bb0, acc[2*q][0]);
                acc[2*q][1]   = ffma2(aa.x, bb1, acc[2*q][1]);
                acc[2*q][2]   = ffma2(aa.x, bb2, acc[2*q][2]);
                acc[2*q][3]   = ffma2(aa.x, bb3, acc[2*q][3]);
                acc[2*q+1][0] = ffma2(aa.y, bb0, acc[2*q+1][0]);
                acc[2*q+1][1] = ffma2(aa.y, bb1, acc[2*q+1][1]);
                acc[2*q+1][2] = ffma2(aa.y, bb2, acc[2*q+1][2]);
                acc[2*q+1][3] = ffma2(aa.y, bb3, acc[2*q+1][3]);
            }
        }

        if (t + 1 < nt) {
            const int nxt = cur ^ 1;
#pragma unroll
            for (int l = 0; l < 4; l++) As2[nxt][ak[l]][am[l]] = pk2(a_r[l], a_r[l]);
#pragma unroll
            for (int l = 0; l < 4; l++) *(float4*)&Bs[nxt][brow[l]][bcol[l]] = b_r[l];
        }
    }
    float* Pp = P + (size_t)blockIdx.y * 64 * (size_t)N;
#pragma unroll
    for (int i = 0; i < 8; i++) {
        size_t base = (size_t)(mbase + i) * N + n0 + nbase;
        *(ull*)&Pp[base]     = acc[i][0];
        *(ull*)&Pp[base + 2] = acc[i][1];
        *(ull*)&Pp[base + 4] = acc[i][2];
        *(ull*)&Pp[base + 6] = acc[i][3];
    }
}

// ---------------- split-K reduce + bias (+ optional tanh-gelu), float4 ----------------
__global__ void __launch_bounds__(256) reduce4_kernel(
    const float* __restrict__ P, int S, int total4, int N4,
    const float* __restrict__ bias, float* __restrict__ dst, int act)
{
    int idx = blockIdx.x * 256 + threadIdx.x;
    if (idx >= total4) return;
    const float4* P4 = (const float4*)P;
    float4 v = make_float4(0.f, 0.f, 0.f, 0.f);
    for (int s = 0; s < S; s++) {
        float4 p = P4[(size_t)s * total4 + idx];
        v.x += p.x; v.y += p.y; v.z += p.z; v.w += p.w;
    }
    float4 bb = ((const float4*)bias)[idx % N4];
    v.x += bb.x; v.y += bb.y; v.z += bb.z; v.w += bb.w;
    if (act == 1) {
        float* f = (float*)&v;
#pragma unroll
        for (int j = 0; j < 4; j++) {
            float x = f[j];
            float x3 = x * x * x;
            f[j] = 0.5f * x * (1.0f + tanhf(0.7978845608028654f * (x + 0.044715f * x3)));
        }
    }
    ((float4*)dst)[idx] = v;
}

// ---------------- attention: cross-item pipelined bulk-TMA, chunk-major K buffer ----------------
// Flat tile stream per CTA: items w, w+296, ..., each = 4 tiles of 32 rows.
// Stages are reloaded with a lookahead of 2 tiles ACROSS item boundaries; q is
// double-buffered and prefetched one item ahead. mbarrier phases flip uniformly.
#define TILE_R 32
#define TILE_F (TILE_R * 256)      // 8192 floats = 32KB
#define ATTN_T 256
#define XSTRIDE 132
#define GSTRIDE 296

__global__ void __launch_bounds__(ATTN_T, 2) attn_kernel(
    const float* __restrict__ past, const float* __restrict__ qkv,
    const int* __restrict__ key_length,
    float* __restrict__ out_kv,
    float* __restrict__ m_part, float* __restrict__ l_part, float* __restrict__ acc_part)
{
    extern __shared__ float sm[];
    float* qbuf[2] = { sm, sm + 2048 };       // double-buffered q
    float* kbuf = sm + 4096 + 16;             // 4096 floats, chunk-major K / merge buf
    float* stg0 = kbuf + 4096;                // linear stage 0 (8192 floats)
    float* stg1 = stg0 + TILE_F;              // linear stage 1
    const uint32_t mb0 = s2u(sm + 4096);
    const uint32_t mb1 = mb0 + 8;

    const int tid = threadIdx.x, lane = tid & 31, warp = tid >> 5;
    const int hg = warp >> 1, rg = warp & 1, h0 = hg * 4;
    const int r16 = lane & 15, hs = lane >> 4;
    const int myrow = rg * 16 + r16;
    const int upd = key_length[0] - 1;
    const float qscale = 0.08838834764831845f;

    if (tid == 0) { MBAR_INIT(mb0, 1); MBAR_INIT(mb1, 1); }
    __syncthreads();
    int ph0 = 0, ph1 = 0;
    int qcur = 0;

    // ---- prime: first item's q + tiles 0,1 ----
    {
        const int w0 = blockIdx.x;
        const float* qb = qkv + (size_t)(w0 >> 5) * QKV_N;
        for (int i = tid; i < 2048; i += ATTN_T)
            qbuf[0][i] = qb[i] * qscale;
        if (tid == 0) {
            const char* src_b = (const char*)past + ((size_t)(w0 >> 5) * KV_LEN) * 1024;
            const int kvbase = (w0 & 31) * 128;
            MBAR_EXPECT(mb0, TILE_F * 4);
            bulk_load(s2u(stg0), src_b + (size_t)kvbase * 1024, TILE_F * 4, mb0);
            MBAR_EXPECT(mb1, TILE_F * 4);
            bulk_load(s2u(stg1), src_b + (size_t)(kvbase + 32) * 1024, TILE_F * 4, mb1);
        }
    }

    for (int w = blockIdx.x; w < B_SZ * NITEM; w += GSTRIDE) {
        const int b = w >> 5, sp = w & 31;
        const float4* qnew = (const float4*)(qkv + (size_t)b * QKV_N + D_MODEL);
        const char* src_b = (const char*)past   + ((size_t)b * KV_LEN) * 1024;
        char*       dst_b = (char*)      out_kv + ((size_t)b * KV_LEN) * 1024;
        const int kvbase = sp * 128;
        const float* q_s = qbuf[qcur];

        const int wn = w + GSTRIDE;
        const bool has_next = (wn < B_SZ * NITEM);
        const char* src_n = has_next
            ? (const char*)past + ((size_t)(wn >> 5) * KV_LEN) * 1024 : nullptr;
        const int kvb_n = (wn & 31) * 128;

        float m0 = -3.4e38f, m1 = -3.4e38f, l0 = 0.f, l1 = 0.f;
        ull acc0[4], acc1[4];
#pragma unroll
        for (int i = 0; i < 4; i++) { acc0[i] = 0ULL; acc1[i] = 0ULL; }

#pragma unroll 1
        for (int t = 0; t < 4; t++) {
            const int st = t & 1;
            float* s = st ? stg1 : stg0;
            if (st) { mbar_wait(mb1, ph1); ph1 ^= 1; }
            else    { mbar_wait(mb0, ph0); ph0 ^= 1; }
            const int kv0 = kvbase + t * 32;
            const bool hasupd = (upd >= kv0 && upd < kv0 + TILE_R);

            // rare: patch the updated KV row into the linear stage
            if (hasupd && tid < 64) {
                float4 val = qnew[tid];
                *(float4*)(s + (upd - kv0) * 256 + tid * 4) = val;
            }
            __syncthreads();   // patch visible; kbuf free (prev compute / merge done)

            if (tid == 0) {
                if (hasupd) asm volatile("fence.proxy.async.shared::cta;" ::: "memory");
                bulk_store(dst_b + (size_t)kv0 * 1024, s2u(s), TILE_F * 4);
                BULK_COMMIT();
            }

            // repack K only: linear stage -> chunk-major kbuf (quad-xor)
#pragma unroll
            for (int li = 0; li < 4; li++) {
                int r = warp + li * 8;
                float4 val = *(const float4*)(s + r * 256 + lane * 4);
                *(float4*)(kbuf + ((lane * 32 + (r ^ (lane & 7))) << 2)) = val;
            }
            __syncthreads();   // kbuf ready

            // prefetch q for next item during tile 2 (after current q reads are pipelined;
            // writes go to the other buffer, no race)
            if (t == 2 && has_next) {
                const float* qbn = qkv + (size_t)(wn >> 5) * QKV_N;
                float* qd = qbuf[qcur ^ 1];
                for (int i = tid; i < 2048; i += ATTN_T)
                    qd[i] = qbn[i] * qscale;
            }

            // ---- scores from kbuf (chunk-major) ----
            const float* qA = q_s + (h0 + 2 * hs) * HDIM;
            const float* qB = qA + HDIM;
            ull xa0 = 0ULL, xa1 = 0ULL, xb0 = 0ULL, xb1 = 0ULL;
#pragma unroll 8
            for (int d4 = 0; d4 < 32; d4++) {
                ulonglong2 k2 = *(const ulonglong2*)(kbuf + ((d4 * 32 + (myrow ^ (d4 & 7))) << 2));
                ulonglong2 qa2 = *(const ulonglong2*)(qA + d4 * 4);
                ulonglong2 qb2 = *(const ulonglong2*)(qB + d4 * 4);
                xa0 = ffma2(k2.x, qa2.x, xa0);
                xa1 = ffma2(k2.y, qa2.y, xa1);
                xb0 = ffma2(k2.x, qb2.x, xb0);
                xb1 = ffma2(k2.y, qb2.y, xb1);
            }
            ull xap = add2(xa0, xa1), xbp = add2(xb0, xb1);
            float xal, xah, xbl, xbh;
            upk2(xal, xah, xap);
            upk2(xbl, xbh, xbp);
            float xa = xal + xah, xb = xbl + xbh;

            float ta = xa, tb = xb;
#pragma unroll
            for (int o = 8; o; o >>= 1) {
                ta = fmaxf(ta, __shfl_xor_sync(0xffffffffu, ta, o));
                tb = fmaxf(tb, __shfl_xor_sync(0xffffffffu, tb, o));
            }
            float mna = fmaxf(m0, ta), mnb = fmaxf(m1, tb);
            float ca = __expf(m0 - mna), cb = __expf(m1 - mnb);
            float pa = __expf(xa - mna), pb = __expf(xb - mnb);
            float sa = pa, sb = pb;
#pragma unroll
            for (int o = 8; o; o >>= 1) {
                sa += __shfl_xor_sync(0xffffffffu, sa, o);
                sb += __shfl_xor_sync(0xffffffffu, sb, o);
            }
            l0 = l0 * ca + sa;  l1 = l1 * cb + sb;
            m0 = mna;           m1 = mnb;
            ull ca2 = pk2(ca, ca), cb2 = pk2(cb, cb);
#pragma unroll
            for (int i = 0; i < 4; i++) { acc0[i] = mul2(acc0[i], ca2); acc1[i] = mul2(acc1[i], cb2); }

            // ---- P @ V directly from the linear stage (conflict-free) ----
            const int rowbase = rg * 16;
#pragma unroll
            for (int r = 0; r < 16; r++) {
                int src = (lane & 16) | r;
                float p0 = __shfl_sync(0xffffffffu, pa, src);
                float p1 = __shfl_sync(0xffffffffu, pb, src);
                ull p02 = pk2(p0, p0), p12 = pk2(p1, p1);
                const float* vr = s + (rowbase + r) * 256 + 128;
                ulonglong2 v01 = *(const ulonglong2*)(vr + r16 * 4);
                ulonglong2 v23 = *(const ulonglong2*)(vr + 64 + r16 * 4);
                acc0[0] = ffma2(p02, v01.x, acc0[0]);
                acc0[1] = ffma2(p02, v01.y, acc0[1]);
                acc0[2] = ffma2(p02, v23.x, acc0[2]);
                acc0[3] = ffma2(p02, v23.y, acc0[3]);
                acc1[0] = ffma2(p12, v01.x, acc1[0]);
                acc1[1] = ffma2(p12, v01.y, acc1[1]);
                acc1[2] = ffma2(p12, v23.x, acc1[2]);
                acc1[3] = ffma2(p12, v23.y, acc1[3]);
            }
            __syncthreads();   // stage fully consumed (V reads + repack done)

            // reload this stage with tile t+2 of the flat stream (crosses item boundary)
            if (tid == 0) {
                const char* ld_src = nullptr;
                if (t < 2)            ld_src = src_b + (size_t)(kvbase + (t + 2) * 32) * 1024;
                else if (has_next)    ld_src = src_n + (size_t)(kvb_n + (t - 2) * 32) * 1024;
                if (ld_src) {
                    BULK_WAIT_READ0();      // this stage's bulk store has read its data
                    uint32_t mb = st ? mb1 : mb0;
                    MBAR_EXPECT(mb, TILE_F * 4);
                    bulk_load(s2u(s), ld_src, TILE_F * 4, mb);
                }
            }
        }

        // ---- in-CTA merge of rg=1 into rg=0 (conflict-free column-major exchange) ----
        ull*   xbuf  = (ull*)kbuf;
        float* mlbuf = kbuf + 2176;
        const int xidx = hg * 32 + lane;
        if (rg == 1) {
#pragma unroll
            for (int i = 0; i < 4; i++) {
                xbuf[i * XSTRIDE + xidx]       = acc0[i];
                xbuf[(4 + i) * XSTRIDE + xidx] = acc1[i];
            }
            float* ml = mlbuf + xidx * 4;
            ml[0] = m0; ml[1] = l0; ml[2] = m1; ml[3] = l1;
        }
        __syncthreads();
        if (rg == 0) {
            const float* ml = mlbuf + xidx * 4;
            float m0b = ml[0], l0b = ml[1], m1b = ml[2], l1b = ml[3];
            float mA = fmaxf(m0, m0b), mB = fmaxf(m1, m1b);
            float c0a = __expf(m0 - mA),  c0b = __expf(m0b - mA);
            float c1a = __expf(m1 - mB),  c1b = __expf(m1b - mB);
            l0 = l0 * c0a + l0b * c0b;
            l1 = l1 * c1a + l1b * c1b;
            ull c0a2 = pk2(c0a, c0a), c0b2 = pk2(c0b, c0b);
            ull c1a2 = pk2(c1a, c1a), c1b2 = pk2(c1b, c1b);
#pragma unroll
            for (int i = 0; i < 4; i++) {
                acc0[i] = add2(mul2(acc0[i], c0a2), mul2(xbuf[i * XSTRIDE + xidx],       c0b2));
                acc1[i] = add2(mul2(acc1[i], c1a2), mul2(xbuf[(4 + i) * XSTRIDE + xidx], c1b2));
            }
            const int ghA = h0 + 2 * hs, ghB = ghA + 1;
            const int phA = (b * N_HEAD + ghA) * NITEM + sp;
            const int phB = (b * N_HEAD + ghB) * NITEM + sp;
            if (r16 == 0) {
                m_part[phA] = mA; l_part[phA] = l0;
                m_part[phB] = mB; l_part[phB] = l1;
            }
            ull* dA = (ull*)(acc_part + (size_t)phA * HDIM);
            ull* dB = (ull*)(acc_part + (size_t)phB * HDIM);
            dA[r16 * 2]          = acc0[0];
            dA[r16 * 2 + 1]      = acc0[1];
            dA[32 + r16 * 2]     = acc0[2];
            dA[32 + r16 * 2 + 1] = acc0[3];
            dB[r16 * 2]          = acc1[0];
            dB[r16 * 2 + 1]      = acc1[1];
            dB[32 + r16 * 2]     = acc1[2];
            dB[32 + r16 * 2 + 1] = acc1[3];
        }
        qcur ^= 1;
    }
}

// ---------------- combine split partial softmax results ----------------
__global__ void __launch_bounds__(128) attn_combine_kernel(
    const float* __restrict__ m_part, const float* __restrict__ l_part,
    const float* __restrict__ acc_part, float* __restrict__ attn_out)
{
    const int bh = blockIdx.x;
    const int d = threadIdx.x;
    float mm = -3.4e38f;
#pragma unroll 8
    for (int s = 0; s < NPART; s++) mm = fmaxf(mm, m_part[bh * NPART + s]);
    float L = 0.f, o = 0.f;
#pragma unroll 8
    for (int s = 0; s < NPART; s++) {
        float w = __expf(m_part[bh * NPART + s] - mm);
        L += l_part[bh * NPART + s] * w;
        o += acc_part[(size_t)(bh * NPART + s) * HDIM + d] * w;
    }
    int b = bh >> 4, h = bh & 15;
    attn_out[(size_t)b * D_MODEL + h * HDIM + d] = o / L;
}

// ---------------- launch ----------------
extern "C" void kernel_launch(void* const* d_in, const int* in_sizes, int n_in,
                              void* d_out, int out_size)
{
    const float* hidden = (const float*)d_in[0];
    const float* resid  = (const float*)d_in[1];
    const float* past   = (const float*)d_in[2];
    // d_in[3] = attention_mask (all-true; no-op)
    const int*   keylen = (const int*)d_in[4];
    const float* aaw = (const float*)d_in[5];
    const float* aab = (const float*)d_in[6];
    const float* apw = (const float*)d_in[7];
    const float* apb = (const float*)d_in[8];
    const float* l1w = (const float*)d_in[9];
    const float* l1b = (const float*)d_in[10];
    const float* l2w = (const float*)d_in[11];
    const float* l2b = (const float*)d_in[12];
    const float* mfw = (const float*)d_in[13];
    const float* mfb = (const float*)d_in[14];
    const float* mpw = (const float*)d_in[15];
    const float* mpb = (const float*)d_in[16];

    float* out     = (float*)d_out;
    float* out_hs  = out;
    float* out_res = out + B_SZ * D_MODEL;
    float* out_kv  = out + 2 * B_SZ * D_MODEL;

    float *res1, *hs1, *qkv, *attn, *hs2, *mid, *part, *pm, *pl, *pacc;
    cudaGetSymbolAddress((void**)&res1, g_res1);
    cudaGetSymbolAddress((void**)&hs1,  g_hs1);
    cudaGetSymbolAddress((void**)&qkv,  g_qkv);
    cudaGetSymbolAddress((void**)&attn, g_attn);
    cudaGetSymbolAddress((void**)&hs2,  g_hs2);
    cudaGetSymbolAddress((void**)&mid,  g_mid);
    cudaGetSymbolAddress((void**)&part, g_part);
    cudaGetSymbolAddress((void**)&pm,   g_m);
    cudaGetSymbolAddress((void**)&pl,   g_l);
    cudaGetSymbolAddress((void**)&pacc, g_acc);

    const int attn_smem = (4096 + 16 + 4096 + 2 * TILE_F) * sizeof(float);   // ~98 KB/CTA
    cudaFuncSetAttribute(attn_kernel, cudaFuncAttributeMaxDynamicSharedMemorySize, attn_smem);

    // 1) residual = hidden + residual ; hs1 = LN1(residual)
    add_ln_kernel<<<64, 256>>>(hidden, resid, l1w, l1b, res1, hs1);

    // 2) qkv = hs1 @ aaw + aab
    gemm_splitk_kernel<<<dim3(9, 32), 256>>>(hs1, aaw, part, 2048, 2304, 64);
    reduce4_kernel<<<(B_SZ * QKV_N / 4 + 255) / 256, 256>>>(part, 32, B_SZ * QKV_N / 4, QKV_N / 4, aab, qkv, 0);

    // 3) attention + KV-cache update + fused layer_past copy-out
    attn_kernel<<<GSTRIDE, ATTN_T, attn_smem>>>(past, qkv, keylen, out_kv, pm, pl, pacc);
    attn_combine_kernel<<<B_SZ * N_HEAD, 128>>>(pm, pl, pacc, attn);

    // 4+5) proj reduce + bias + residual-add + LN2 (fused)
    gemm_splitk_kernel<<<dim3(8, 32), 256>>>(attn, apw, part, 2048, 2048, 64);
    freduce_ln_kernel<<<64, 512>>>(part, 32, apb, res1, l2w, l2b, out_res, hs2);

    // 6) mid = gelu(hs2 @ mfw + mfb)
    gemm_splitk_kernel<<<dim3(32, 8), 256>>>(hs2, mfw, part, 2048, 8192, 256);
    reduce4_kernel<<<(B_SZ * FF_DIM / 4 + 255) / 256, 256>>>(part, 8, B_SZ * FF_DIM / 4, FF_DIM / 4, mfb, mid, 1);

    // 7) out_hs = mid @ mpw + mpb
    gemm_splitk_kernel<<<dim3(8, 32), 256>>>(mid, mpw, part, 8192, 2048, 256);
    reduce4_kernel<<<(B_SZ * D_MODEL / 4 + 255) / 256, 256>>>(part, 32, B_SZ * D_MODEL / 4, D_MODEL / 4, mpb, out_hs, 0);
}